// round 11
// baseline (speedup 1.0000x reference)
#include <cuda_runtime.h>
#include <cuda_bf16.h>
#include <math.h>
#include <stdint.h>

#define BATCH 256
#define GSZ   60
#define KSZ   13
#define NTOT  (BATCH * GSZ)    // 15360 per net
#define NTOT2 (2 * NTOT)       // 30720 both nets

#define OFF_F0 0
#define OFF_F1 491520
#define OFF_E0 983040
#define OFF_E1 1474560
#define OFF_I0 1966080
#define OFF_I1 1974272
#define OFF_AB 1982464
#define OFF_TI 1982465
#define OFF_PI 1982721

// ---------------------------------------------------------------------------
// Device scratch.
// Weights: Wp[o][s][hi64 | lo64] bf16, s = j*13+k (chunk-major).
// Acts:    actP[n][j][hi64 | lo64] bf16, n = net*15360 + b*60 + g.
// ---------------------------------------------------------------------------
__device__ __nv_bfloat16 g_WpI[256 * 13 * 128];
__device__ __nv_bfloat16 g_Wp1[512 * 52 * 128];
__device__ __nv_bfloat16 g_Wp2[256 * 104 * 128];
__device__ __nv_bfloat16 g_WpO[128 * 52 * 128];
__device__ __nv_bfloat16 g_fP [NTOT2 * 1 * 128];
__device__ __nv_bfloat16 g_dP [NTOT2 * 4 * 128];
__device__ __nv_bfloat16 g_f1P[NTOT2 * 8 * 128];
__device__ __nv_bfloat16 g_d2P[NTOT2 * 4 * 128];
__device__ float g_dT32[NTOT2 * 256];
__device__ float g_epT [NTOT2 * 32];
__device__ float g_e0  [BATCH * 32 * GSZ];
__device__ float g_e1  [BATCH * 32 * GSZ];
__device__ int   g_pre [BATCH];

// ---- helpers ----
__device__ __forceinline__ uint32_t smem_u32(const void* p) {
    uint32_t a;
    asm("{ .reg .u64 t; cvta.to.shared.u64 t, %1; cvt.u32.u64 %0, t; }" : "=r"(a) : "l"(p));
    return a;
}
#define SWZ(x) ((x) ^ (((x) >> 3) & 0x70))

__device__ __forceinline__ void cpasync16(uint32_t dst, const void* src) {
    asm volatile("cp.async.ca.shared.global [%0], [%1], 16;" :: "r"(dst), "l"(src) : "memory");
}
__device__ __forceinline__ void cp_commit() {
    asm volatile("cp.async.commit_group;" ::: "memory");
}
__device__ __forceinline__ void cp_wait1() {
    asm volatile("cp.async.wait_group 1;" ::: "memory");
}
__device__ __forceinline__ void ldsm4(uint32_t* r, uint32_t a) {
    asm volatile("ldmatrix.sync.aligned.m8n8.x4.shared.b16 {%0,%1,%2,%3}, [%4];"
                 : "=r"(r[0]), "=r"(r[1]), "=r"(r[2]), "=r"(r[3]) : "r"(a));
}
__device__ __forceinline__ void ldsm2(uint32_t* r, uint32_t a) {
    asm volatile("ldmatrix.sync.aligned.m8n8.x2.shared.b16 {%0,%1}, [%2];"
                 : "=r"(r[0]), "=r"(r[1]) : "r"(a));
}
__device__ __forceinline__ void mma_bf(float* d, const uint32_t* a, const uint32_t* b) {
    asm volatile(
        "mma.sync.aligned.m16n8k16.row.col.f32.bf16.bf16.f32 "
        "{%0,%1,%2,%3},{%4,%5,%6,%7},{%8,%9},{%0,%1,%2,%3};"
        : "+f"(d[0]), "+f"(d[1]), "+f"(d[2]), "+f"(d[3])
        : "r"(a[0]), "r"(a[1]), "r"(a[2]), "r"(a[3]), "r"(b[0]), "r"(b[1]));
}
__device__ __forceinline__ void split_bf(float v, __nv_bfloat16& h, __nv_bfloat16& l) {
    h = __float2bfloat16(v);
    l = __float2bfloat16(v - __bfloat162float(h));
}

// ---- prep: W[o][cr][k] -> Wp[o][s][hi64|lo64], s=j*13+k ----
__global__ __launch_bounds__(256) void prep_w(
    __nv_bfloat16* __restrict__ dst, const float* __restrict__ W,
    int Oreal, int Creal, int nstages)
{
    int idx = blockIdx.x * 256 + threadIdx.x;
    int c = idx & 63;
    int s = (idx >> 6) % nstages;
    int o = idx / (64 * nstages);
    int k = s % 13, j = s / 13;
    int cr = j * 64 + c;
    float v = 0.f;
    if (o < Oreal && cr < Creal) v = W[((size_t)o * Creal + cr) * 13 + k];
    __nv_bfloat16 h, l; split_bf(v, h, l);
    size_t base = ((size_t)o * nstages + s) * 128;
    dst[base + c] = h;
    dst[base + 64 + c] = l;
}

// ---- prep: feats[b][c][g] -> dst[n][hi64|lo64] ----
__global__ __launch_bounds__(256) void prep_feats(
    __nv_bfloat16* __restrict__ dst, const float* __restrict__ f)
{
    int idx = blockIdx.x * 256 + threadIdx.x;   // < 15360*64
    int c = idx & 63;
    int n = idx >> 6;
    int b = n / 60, g = n - b * 60;
    float v = (c < 32) ? f[(size_t)b * 1920 + c * 60 + g] : 0.f;
    __nv_bfloat16 h, l; split_bf(v, h, l);
    size_t base = (size_t)n * 128;
    dst[base + c] = h;
    dst[base + 64 + c] = l;
}

// ---------------------------------------------------------------------------
// Gather-fused GEMM, 3-pass bf16 hi/lo mma.sync.
// CTA tile M=128 x N=128; 8 warps (2M x 4N), warp 64x32.
// A: 2-stage cp.async ring (32KB/stage, SW128 swizzled).
// B: per-chunk row cache (<=240 rows x 272B; hi|lo 128B each), double-buffered;
//    k-gather done by per-lane ldmatrix row addresses from lut.
// One commit group per stage; wait_group 1 in the loop.
// ---------------------------------------------------------------------------
#define OFF_A    8192
#define STG_A    32768
#define OFF_BC   (OFF_A + 2 * STG_A)      // 73728
#define BC_SZ    65280                    // 240 rows * 272B
#define SMEM_DYN (OFF_BC + 2 * BC_SZ)     // 204288

__global__ __launch_bounds__(256, 1) void gf_gemm(
    const __nv_bfloat16* __restrict__ Wp, const __nv_bfloat16* __restrict__ actP,
    int nch, int nstages, const int* __restrict__ nei, int mode,
    const float* __restrict__ bias, const float* __restrict__ gamma,
    const float* __restrict__ beta, const float* __restrict__ dres,
    const float* __restrict__ feats0, const float* __restrict__ feats1,
    float* __restrict__ out32, __nv_bfloat16* __restrict__ actOut, int nchO)
{
    extern __shared__ __align__(1024) char smem[];
    int* lut = (int*)smem;                    // [13][128] byte offsets (row*272)
    const uint32_t su = smem_u32(smem);
    const int tid = threadIdx.x;
    const int warp = tid >> 5, lane = tid & 31;
    const int n0 = blockIdx.x * 128;          // global position (both nets)
    const int m0 = blockIdx.y * 128;

    const int net  = n0 / NTOT;
    const int n0w  = n0 - net * NTOT;
    const int b0   = n0w / 60;
    const int bcnt = (n0w + 127) / 60 - b0 + 1;     // <= 4
    const size_t p0 = (size_t)net * NTOT + (size_t)b0 * 60;

    if (tid < 128) {
        const int nw = n0w + tid;
        const int b = nw / 60, g = nw - b * 60;
        #pragma unroll
        for (int k = 0; k < KSZ; ++k)
            lut[k * 128 + tid] = ((b - b0) * 60 + nei[g * KSZ + k]) * 272;
    }
    __syncthreads();

    const int row = tid >> 1;          // 0..127
    const int half = tid & 1;          // 0: hi, 1: lo

    auto load_A = [&](int s) {
        const uint32_t ab = su + OFF_A + (uint32_t)(s & 1) * STG_A;
        const char* src = (const char*)(Wp + ((size_t)(m0 + row) * nstages + s) * 128)
                          + half * 128;
        const uint32_t dst = ab + half * 16384;
        #pragma unroll
        for (int c = 0; c < 8; ++c)
            cpasync16(dst + SWZ((uint32_t)(row * 128 + c * 16)), src + c * 16);
    };
    auto load_cache = [&](int j) {
        const uint32_t cb = su + OFF_BC + (uint32_t)(j & 1) * BC_SZ;
        const char* src0 = (const char*)actP + ((size_t)p0 * nch + j) * 256;
        const int tot = bcnt * 60 * 16;
        const size_t rstride = (size_t)nch * 256;
        for (int i = tid; i < tot; i += 256) {
            const int r = i >> 4, c = i & 15;
            cpasync16(cb + (uint32_t)(r * 272 + c * 16), src0 + (size_t)r * rstride + c * 16);
        }
    };

    // prologue: group0 = cache0 + A0; group1 = cache1(if any) + A1(if any)
    load_cache(0); load_A(0); cp_commit();
    if (nch > 1) load_cache(1);
    if (1 < nstages) load_A(1);
    cp_commit();

    const int wm = warp >> 2, wn = warp & 3;
    float acc[4][4][4] = {};

    const uint32_t arow = (uint32_t)(wm * 64 + (lane & 15));
    const uint32_t acolx = (uint32_t)((lane >> 4) * 16);
    const uint32_t bhalf16 = (uint32_t)(((lane >> 3) & 1) * 16);
    const int nll = lane & 7;

    for (int s = 0; s < nstages; ++s) {
        cp_wait1();
        __syncthreads();
        const int k = s % 13;
        const uint32_t ab = su + OFF_A + (uint32_t)(s & 1) * STG_A;
        const uint32_t cb = su + OFF_BC + (uint32_t)((s / 13) & 1) * BC_SZ;
        const uint32_t Ah = ab, Al = ab + 16384;

        int lofs[4];
        #pragma unroll
        for (int nt = 0; nt < 4; ++nt)
            lofs[nt] = lut[k * 128 + wn * 32 + nt * 8 + nll];

        #pragma unroll
        for (int ks = 0; ks < 4; ++ks) {
            const uint32_t kb = ks * 32;
            uint32_t ah[4][4], al[4][4], bh[4][2], bl[4][2];
            #pragma unroll
            for (int mt = 0; mt < 4; ++mt) {
                const uint32_t off = SWZ((arow + mt * 16) * 128 + kb + acolx);
                ldsm4(ah[mt], Ah + off);
                ldsm4(al[mt], Al + off);
            }
            #pragma unroll
            for (int nt = 0; nt < 4; ++nt) {
                const uint32_t ba = cb + (uint32_t)lofs[nt] + kb + bhalf16;
                ldsm2(bh[nt], ba);            // hi plane (first 128B of row)
                ldsm2(bl[nt], ba + 128);      // lo plane
            }
            #pragma unroll
            for (int mt = 0; mt < 4; ++mt)
                #pragma unroll
                for (int nt = 0; nt < 4; ++nt) {
                    mma_bf(acc[mt][nt], ah[mt], bh[nt]);
                    mma_bf(acc[mt][nt], ah[mt], bl[nt]);
                    mma_bf(acc[mt][nt], al[mt], bh[nt]);
                }
        }
        __syncthreads();
        if (s + 2 < nstages) load_A(s + 2);
        if (k == 12 && (s / 13) + 2 < nch) load_cache((s / 13) + 2);
        cp_commit();
    }

    // ---- epilogue ----
    const int g4 = lane >> 2, t4 = lane & 3;
    #pragma unroll
    for (int mt = 0; mt < 4; ++mt) {
        #pragma unroll
        for (int dr = 0; dr < 2; ++dr) {
            const int o = m0 + wm * 64 + mt * 16 + g4 + dr * 8;
            if (mode == 3 && o >= 32) continue;
            const float bv = bias[o];
            float gv = 0.f, bev = 0.f;
            if (mode != 0) { gv = gamma[o]; bev = beta[o]; }
            const int jo = o >> 6, co = o & 63;
            #pragma unroll
            for (int nt = 0; nt < 4; ++nt) {
                #pragma unroll
                for (int dn = 0; dn < 2; ++dn) {
                    const float sv = acc[mt][nt][dr * 2 + dn] + bv;
                    const int n = n0 + wn * 32 + nt * 8 + t4 * 2 + dn;
                    if (mode == 0) {
                        out32[(size_t)n * 256 + o] = sv;
                        __nv_bfloat16 h, l; split_bf(sv, h, l);
                        const size_t base = ((size_t)n * nchO + jo) * 128;
                        actOut[base + co] = h; actOut[base + 64 + co] = l;
                    } else if (mode == 1) {
                        const float v = fmaxf(sv * gv + bev, 0.f);
                        __nv_bfloat16 h, l; split_bf(v, h, l);
                        const size_t base = ((size_t)n * nchO + jo) * 128;
                        actOut[base + co] = h; actOut[base + 64 + co] = l;
                    } else if (mode == 2) {
                        const float v = fmaxf(sv * gv + bev, 0.f) + dres[(size_t)n * 256 + o];
                        __nv_bfloat16 h, l; split_bf(v, h, l);
                        const size_t base = ((size_t)n * nchO + jo) * 128;
                        actOut[base + co] = h; actOut[base + 64 + co] = l;
                    } else {
                        const int netl = n / NTOT;
                        const int nw = n - netl * NTOT;
                        const int b = nw / 60, gg = nw - b * 60;
                        const float* fsrc = netl ? feats1 : feats0;
                        out32[(size_t)n * 32 + o] =
                            fmaxf(sv * gv + bev, 0.f) + fsrc[(size_t)b * 1920 + o * 60 + gg];
                    }
                }
            }
        }
    }
}

// ---- finalize: epT[(b,g)][32] -> inv + normalized eqv [b][c][g] ----
__global__ __launch_bounds__(64) void finalize_t(
    const float* __restrict__ epT, float* __restrict__ e_store,
    float* __restrict__ out_eqv, float* __restrict__ out_inv)
{
    __shared__ float s[1920];
    __shared__ float norms[60];
    __shared__ float invv[32];
    __shared__ float ninv;
    const int b = blockIdx.x, t = threadIdx.x;

    for (int i = t; i < 1920; i += 64) s[i] = epT[(size_t)b * 1920 + i];
    __syncthreads();
    if (t < 60) {
        float a = 0.f;
        #pragma unroll
        for (int c = 0; c < 32; ++c) { float v = s[t * 32 + c]; a += v * v; }
        norms[t] = fmaxf(sqrtf(a), 1e-4f);
    }
    if (t < 32) {
        float a = 0.f;
        for (int g = 0; g < 60; ++g) a += s[g * 32 + t];
        invv[t] = a * (1.f / 60.f);
    }
    __syncthreads();
    if (t == 0) {
        float a = 0.f;
        #pragma unroll
        for (int c = 0; c < 32; ++c) a += invv[c] * invv[c];
        ninv = fmaxf(sqrtf(a), 1e-4f);
    }
    __syncthreads();
    if (t < 32) out_inv[b * 32 + t] = invv[t] / ninv;
    for (int i = t; i < 1920; i += 64) {
        const int g = i >> 5, c = i & 31;
        const float v = s[i] / norms[g];
        const size_t oi = (size_t)b * 1920 + c * 60 + g;
        out_eqv[oi] = v;
        e_store[oi] = v;
    }
}

// ---- des2dr ----
__global__ __launch_bounds__(64) void des2dr_kernel(
    const float* __restrict__ e0, const float* __restrict__ e1,
    const int* __restrict__ permu, int* __restrict__ pre)
{
    __shared__ float s0[1920], s1[1920];
    __shared__ float cor[60];
    __shared__ int sp[3600];
    const int b = blockIdx.x, t = threadIdx.x;

    for (int i = t; i < 1920; i += 64) {
        s0[i] = e0[(size_t)b * 1920 + i];
        s1[i] = e1[(size_t)b * 1920 + i];
    }
    for (int i = t; i < 3600; i += 64) sp[i] = permu[i];
    __syncthreads();

    if (t < 60) {
        float a = 0.f;
        for (int g = 0; g < 60; ++g) {
            const int p = sp[t * 60 + g];
            #pragma unroll 8
            for (int f = 0; f < 32; ++f) a += s0[f * 60 + p] * s1[f * 60 + g];
        }
        cor[t] = a;
    }
    __syncthreads();
    if (t == 0) {
        float best = cor[0]; int bi = 0;
        for (int a = 1; a < 60; ++a) if (cor[a] > best) { best = cor[a]; bi = a; }
        pre[b] = bi;
    }
}

// ---- ability + integer outputs ----
__global__ __launch_bounds__(256) void final_kernel(
    const int* __restrict__ pre, const int* __restrict__ truei,
    float* __restrict__ out)
{
    __shared__ int cnt[256];
    const int t = threadIdx.x;
    cnt[t] = (pre[t] == truei[t]) ? 1 : 0;
    __syncthreads();
    for (int s = 128; s > 0; s >>= 1) {
        if (t < s) cnt[t] += cnt[t + s];
        __syncthreads();
    }
    if (t == 0) out[OFF_AB] = (float)cnt[0] / 256.f;
    out[OFF_TI + t] = (float)truei[t];
    out[OFF_PI + t] = (float)pre[t];
}

// ---------------------------------------------------------------------------
extern "C" void kernel_launch(void* const* d_in, const int* in_sizes, int n_in,
                              void* d_out, int out_size)
{
    const float* feats0 = (const float*)d_in[0];
    const float* feats1 = (const float*)d_in[1];
    const int*   truei  = (const int*)  d_in[2];
    const int*   nei    = (const int*)  d_in[3];
    const int*   permu  = (const int*)  d_in[4];
    const float* W_in = (const float*)d_in[5];  const float* b_in = (const float*)d_in[6];
    const float* W1   = (const float*)d_in[7];  const float* b1   = (const float*)d_in[8];
    const float* g1   = (const float*)d_in[9];  const float* be1  = (const float*)d_in[10];
    const float* W2   = (const float*)d_in[11]; const float* b2   = (const float*)d_in[12];
    const float* g2   = (const float*)d_in[13]; const float* be2  = (const float*)d_in[14];
    const float* Wo   = (const float*)d_in[15]; const float* bo   = (const float*)d_in[16];
    const float* go   = (const float*)d_in[17]; const float* beo  = (const float*)d_in[18];
    float* out = (float*)d_out;

    __nv_bfloat16 *WpI, *Wp1, *Wp2, *WpO, *fP, *dP, *f1P, *d2P;
    float *dT32, *epT, *e0, *e1;
    int* pre;
    cudaGetSymbolAddress((void**)&WpI,  g_WpI);
    cudaGetSymbolAddress((void**)&Wp1,  g_Wp1);
    cudaGetSymbolAddress((void**)&Wp2,  g_Wp2);
    cudaGetSymbolAddress((void**)&WpO,  g_WpO);
    cudaGetSymbolAddress((void**)&fP,   g_fP);
    cudaGetSymbolAddress((void**)&dP,   g_dP);
    cudaGetSymbolAddress((void**)&f1P,  g_f1P);
    cudaGetSymbolAddress((void**)&d2P,  g_d2P);
    cudaGetSymbolAddress((void**)&dT32, g_dT32);
    cudaGetSymbolAddress((void**)&epT,  g_epT);
    cudaGetSymbolAddress((void**)&e0,   g_e0);
    cudaGetSymbolAddress((void**)&e1,   g_e1);
    cudaGetSymbolAddress((void**)&pre,  g_pre);

    cudaFuncSetAttribute(gf_gemm, cudaFuncAttributeMaxDynamicSharedMemorySize, SMEM_DYN);

    cudaMemcpyAsync(out + OFF_F0, feats0, (size_t)491520 * 4, cudaMemcpyDeviceToDevice, 0);
    cudaMemcpyAsync(out + OFF_F1, feats1, (size_t)491520 * 4, cudaMemcpyDeviceToDevice, 0);

    prep_w<<<(256 * 13 * 64) / 256, 256>>>(WpI, W_in, 256, 32, 13);
    prep_w<<<(512 * 52 * 64) / 256, 256>>>(Wp1, W1, 512, 256, 52);
    prep_w<<<(256 * 104 * 64) / 256, 256>>>(Wp2, W2, 256, 512, 104);
    prep_w<<<(128 * 52 * 64) / 256, 256>>>(WpO, Wo, 32, 256, 52);

    prep_feats<<<(NTOT * 64) / 256, 256>>>(fP, feats0);
    prep_feats<<<(NTOT * 64) / 256, 256>>>(fP + (size_t)NTOT * 128, feats1);

    // conv_in: nch=1, O=256 -> mode 0 (dT32 + dP)
    gf_gemm<<<dim3(240, 2), 256, SMEM_DYN>>>(WpI, fP, 1, 13, nei, 0,
        b_in, b_in, b_in, dT32, feats0, feats1, dT32, dP, 4);
    // layer1: nch=4, O=512 -> mode 1 (f1P)
    gf_gemm<<<dim3(240, 4), 256, SMEM_DYN>>>(Wp1, dP, 4, 52, nei, 1,
        b1, g1, be1, dT32, feats0, feats1, dT32, f1P, 8);
    // layer2: nch=8, O=256 -> mode 2 (residual dT32 -> d2P)
    gf_gemm<<<dim3(240, 2), 256, SMEM_DYN>>>(Wp2, f1P, 8, 104, nei, 2,
        b2, g2, be2, dT32, feats0, feats1, dT32, d2P, 4);
    // conv_out: nch=4, O=32(pad128) -> mode 3 (+feats -> epT)
    gf_gemm<<<dim3(240, 1), 256, SMEM_DYN>>>(WpO, d2P, 4, 52, nei, 3,
        bo, go, beo, dT32, feats0, feats1, epT, dP, 4);

    finalize_t<<<BATCH, 64>>>(epT, e0, out + OFF_E0, out + OFF_I0);
    finalize_t<<<BATCH, 64>>>(epT + (size_t)NTOT * 32, e1, out + OFF_E1, out + OFF_I1);

    des2dr_kernel<<<BATCH, 64>>>(e0, e1, permu, pre);
    final_kernel<<<1, 256>>>(pre, truei, out);
}

// round 12
// speedup vs baseline: 1.5486x; 1.5486x over previous
#include <cuda_runtime.h>
#include <cuda_bf16.h>
#include <math.h>
#include <stdint.h>

#define BATCH 256
#define GSZ   60
#define KSZ   13
#define NTOT  (BATCH * GSZ)    // 15360 per net
#define NTOT2 (2 * NTOT)       // 30720 both nets

#define OFF_F0 0
#define OFF_F1 491520
#define OFF_E0 983040
#define OFF_E1 1474560
#define OFF_I0 1966080
#define OFF_I1 1974272
#define OFF_AB 1982464
#define OFF_TI 1982465
#define OFF_PI 1982721

// ---------------------------------------------------------------------------
// Device scratch.
// Weights: Wp[o][s][hi64 | lo64] bf16, s = j*13+k (chunk-major).
// Acts:    actP[n][j][hi64 | lo64] bf16, n = net*15360 + b*60 + g.
// ---------------------------------------------------------------------------
__device__ __nv_bfloat16 g_WpI[256 * 13 * 128];
__device__ __nv_bfloat16 g_Wp1[512 * 52 * 128];
__device__ __nv_bfloat16 g_Wp2[256 * 104 * 128];
__device__ __nv_bfloat16 g_WpO[128 * 52 * 128];
__device__ __nv_bfloat16 g_fP [NTOT2 * 1 * 128];
__device__ __nv_bfloat16 g_dP [NTOT2 * 4 * 128];
__device__ __nv_bfloat16 g_f1P[NTOT2 * 8 * 128];
__device__ __nv_bfloat16 g_d2P[NTOT2 * 4 * 128];
__device__ float g_dT32[NTOT2 * 256];
__device__ float g_epT [NTOT2 * 32];
__device__ float g_e0  [BATCH * 32 * GSZ];
__device__ float g_e1  [BATCH * 32 * GSZ];
__device__ int   g_pre [BATCH];

// ---- helpers ----
__device__ __forceinline__ uint32_t smem_u32(const void* p) {
    uint32_t a;
    asm("{ .reg .u64 t; cvta.to.shared.u64 t, %1; cvt.u32.u64 %0, t; }" : "=r"(a) : "l"(p));
    return a;
}
#define SWZ(x) ((x) ^ (((x) >> 3) & 0x70))

__device__ __forceinline__ void cpasync16(uint32_t dst, const void* src) {
    asm volatile("cp.async.ca.shared.global [%0], [%1], 16;" :: "r"(dst), "l"(src) : "memory");
}
__device__ __forceinline__ void cp_commit() {
    asm volatile("cp.async.commit_group;" ::: "memory");
}
__device__ __forceinline__ void cp_wait1() {
    asm volatile("cp.async.wait_group 1;" ::: "memory");
}
__device__ __forceinline__ void ldsm4(uint32_t* r, uint32_t a) {
    asm volatile("ldmatrix.sync.aligned.m8n8.x4.shared.b16 {%0,%1,%2,%3}, [%4];"
                 : "=r"(r[0]), "=r"(r[1]), "=r"(r[2]), "=r"(r[3]) : "r"(a));
}
__device__ __forceinline__ void ldsm2(uint32_t* r, uint32_t a) {
    asm volatile("ldmatrix.sync.aligned.m8n8.x2.shared.b16 {%0,%1}, [%2];"
                 : "=r"(r[0]), "=r"(r[1]) : "r"(a));
}
__device__ __forceinline__ void mma_bf(float* d, const uint32_t* a, const uint32_t* b) {
    asm volatile(
        "mma.sync.aligned.m16n8k16.row.col.f32.bf16.bf16.f32 "
        "{%0,%1,%2,%3},{%4,%5,%6,%7},{%8,%9},{%0,%1,%2,%3};"
        : "+f"(d[0]), "+f"(d[1]), "+f"(d[2]), "+f"(d[3])
        : "r"(a[0]), "r"(a[1]), "r"(a[2]), "r"(a[3]), "r"(b[0]), "r"(b[1]));
}
__device__ __forceinline__ void split_bf(float v, __nv_bfloat16& h, __nv_bfloat16& l) {
    h = __float2bfloat16(v);
    l = __float2bfloat16(v - __bfloat162float(h));
}

// ---- prep: W[o][cr][k] -> Wp[o][s][hi64|lo64], s=j*13+k ----
__global__ __launch_bounds__(256) void prep_w(
    __nv_bfloat16* __restrict__ dst, const float* __restrict__ W,
    int Oreal, int Creal, int nstages)
{
    int idx = blockIdx.x * 256 + threadIdx.x;
    int c = idx & 63;
    int s = (idx >> 6) % nstages;
    int o = idx / (64 * nstages);
    int k = s % 13, j = s / 13;
    int cr = j * 64 + c;
    float v = 0.f;
    if (o < Oreal && cr < Creal) v = W[((size_t)o * Creal + cr) * 13 + k];
    __nv_bfloat16 h, l; split_bf(v, h, l);
    size_t base = ((size_t)o * nstages + s) * 128;
    dst[base + c] = h;
    dst[base + 64 + c] = l;
}

// ---- prep: feats[b][c][g] -> dst[n][hi64|lo64] ----
__global__ __launch_bounds__(256) void prep_feats(
    __nv_bfloat16* __restrict__ dst, const float* __restrict__ f)
{
    int idx = blockIdx.x * 256 + threadIdx.x;   // < 15360*64
    int c = idx & 63;
    int n = idx >> 6;
    int b = n / 60, g = n - b * 60;
    float v = (c < 32) ? f[(size_t)b * 1920 + c * 60 + g] : 0.f;
    __nv_bfloat16 h, l; split_bf(v, h, l);
    size_t base = (size_t)n * 128;
    dst[base + c] = h;
    dst[base + 64 + c] = l;
}

// ---------------------------------------------------------------------------
// Gather-fused GEMM, 3-pass bf16 hi/lo mma.sync (round-8 engine, N=256 tile).
// CTA tile M=128 x N=256; 8 warps (2M x 4N), warp tile 64x64.
// Stage = one (chunk j, k): A 32KB (hi|lo) + B 64KB (hi|lo), SW128 swizzled,
// conflict-free ldmatrix. Double-buffered cp.async, one group per stage.
// ---------------------------------------------------------------------------
#define OFF_STG  16384
#define STG_SZ   98304
#define SMEM_DYN (OFF_STG + 2 * STG_SZ)   // 212992

__global__ __launch_bounds__(256, 1) void gf_gemm(
    const __nv_bfloat16* __restrict__ Wp, const __nv_bfloat16* __restrict__ actP,
    int nch, int nstages, const int* __restrict__ nei, int mode,
    const float* __restrict__ bias, const float* __restrict__ gamma,
    const float* __restrict__ beta, const float* __restrict__ dres,
    const float* __restrict__ feats0, const float* __restrict__ feats1,
    float* __restrict__ out32, __nv_bfloat16* __restrict__ actOut, int nchO)
{
    extern __shared__ __align__(1024) char smem[];
    int* lut = (int*)smem;                    // [13][256] absolute act row index
    const uint32_t su = smem_u32(smem);
    const int tid = threadIdx.x;
    const int warp = tid >> 5, lane = tid & 31;
    const int n0 = blockIdx.x * 256;          // global position (both nets)
    const int m0 = blockIdx.y * 128;

    {
        const int n = n0 + tid;
        const int net = n / NTOT;
        const int nw = n - net * NTOT;
        const int b = nw / 60, g = nw - b * 60;
        #pragma unroll
        for (int k = 0; k < KSZ; ++k)
            lut[k * 256 + tid] = net * NTOT + b * 60 + nei[g * KSZ + k];
    }
    __syncthreads();

    const int row = tid >> 1;          // 0..127
    const int half = tid & 1;          // 0: hi, 1: lo

    auto load_stage = [&](int s) {
        const uint32_t bufs = su + OFF_STG + (uint32_t)(s & 1) * STG_SZ;
        // A: 128 rows x 128B per plane
        {
            const char* src = (const char*)(Wp + ((size_t)(m0 + row) * nstages + s) * 128)
                              + half * 128;
            const uint32_t dst = bufs + half * 16384;
            #pragma unroll
            for (int c = 0; c < 8; ++c)
                cpasync16(dst + SWZ((uint32_t)(row * 128 + c * 16)), src + c * 16);
        }
        // B: 256 gathered rows x 128B per plane
        {
            const int k = s % 13, j = s / 13;
            const uint32_t dst = bufs + 32768 + half * 32768;
            #pragma unroll
            for (int rr = 0; rr < 2; ++rr) {
                const int r = rr * 128 + row;
                const int sr = lut[k * 256 + r];
                const char* src = (const char*)(actP + ((size_t)sr * nch + j) * 128)
                                  + half * 128;
                #pragma unroll
                for (int c = 0; c < 8; ++c)
                    cpasync16(dst + SWZ((uint32_t)(r * 128 + c * 16)), src + c * 16);
            }
        }
    };

    // prologue: double buffer
    load_stage(0); cp_commit();
    if (1 < nstages) load_stage(1);
    cp_commit();

    const int wm = warp >> 2, wn = warp & 3;
    float acc[4][8][4] = {};

    const uint32_t arow = (uint32_t)(wm * 64 + (lane & 15));
    const uint32_t acolx = (uint32_t)((lane >> 4) * 16);
    const uint32_t brow = (uint32_t)(wn * 64 + (lane & 7));
    const uint32_t bcolx = (uint32_t)(((lane >> 3) & 1) * 16);

    for (int s = 0; s < nstages; ++s) {
        cp_wait1();
        __syncthreads();
        const uint32_t bufs = su + OFF_STG + (uint32_t)(s & 1) * STG_SZ;
        const uint32_t Ah = bufs, Al = bufs + 16384;
        const uint32_t Bh = bufs + 32768, Bl = bufs + 65536;

        #pragma unroll
        for (int ks = 0; ks < 4; ++ks) {
            const uint32_t kb = ks * 32;
            uint32_t ah[4][4], al[4][4], bh[8][2], bl[8][2];
            #pragma unroll
            for (int mt = 0; mt < 4; ++mt) {
                const uint32_t off = SWZ((arow + mt * 16) * 128 + kb + acolx);
                ldsm4(ah[mt], Ah + off);
                ldsm4(al[mt], Al + off);
            }
            #pragma unroll
            for (int nt = 0; nt < 8; ++nt) {
                const uint32_t off = SWZ((brow + nt * 8) * 128 + kb + bcolx);
                ldsm2(bh[nt], Bh + off);
                ldsm2(bl[nt], Bl + off);
            }
            #pragma unroll
            for (int mt = 0; mt < 4; ++mt)
                #pragma unroll
                for (int nt = 0; nt < 8; ++nt) {
                    mma_bf(acc[mt][nt], ah[mt], bh[nt]);
                    mma_bf(acc[mt][nt], ah[mt], bl[nt]);
                    mma_bf(acc[mt][nt], al[mt], bh[nt]);
                }
        }
        __syncthreads();
        if (s + 2 < nstages) load_stage(s + 2);
        cp_commit();
    }

    // ---- epilogue ----
    const int g4 = lane >> 2, t4 = lane & 3;
    #pragma unroll
    for (int mt = 0; mt < 4; ++mt) {
        #pragma unroll
        for (int dr = 0; dr < 2; ++dr) {
            const int o = m0 + wm * 64 + mt * 16 + g4 + dr * 8;
            if (mode == 3 && o >= 32) continue;
            const float bv = bias[o];
            float gv = 0.f, bev = 0.f;
            if (mode != 0) { gv = gamma[o]; bev = beta[o]; }
            const int jo = o >> 6, co = o & 63;
            #pragma unroll
            for (int nt = 0; nt < 8; ++nt) {
                #pragma unroll
                for (int dn = 0; dn < 2; ++dn) {
                    const float sv = acc[mt][nt][dr * 2 + dn] + bv;
                    const int n = n0 + wn * 64 + nt * 8 + t4 * 2 + dn;
                    if (mode == 0) {
                        out32[(size_t)n * 256 + o] = sv;
                        __nv_bfloat16 h, l; split_bf(sv, h, l);
                        const size_t base = ((size_t)n * nchO + jo) * 128;
                        actOut[base + co] = h; actOut[base + 64 + co] = l;
                    } else if (mode == 1) {
                        const float v = fmaxf(sv * gv + bev, 0.f);
                        __nv_bfloat16 h, l; split_bf(v, h, l);
                        const size_t base = ((size_t)n * nchO + jo) * 128;
                        actOut[base + co] = h; actOut[base + 64 + co] = l;
                    } else if (mode == 2) {
                        const float v = fmaxf(sv * gv + bev, 0.f) + dres[(size_t)n * 256 + o];
                        __nv_bfloat16 h, l; split_bf(v, h, l);
                        const size_t base = ((size_t)n * nchO + jo) * 128;
                        actOut[base + co] = h; actOut[base + 64 + co] = l;
                    } else {
                        const int netl = n / NTOT;
                        const int nw = n - netl * NTOT;
                        const int b = nw / 60, gg = nw - b * 60;
                        const float* fsrc = netl ? feats1 : feats0;
                        out32[(size_t)n * 32 + o] =
                            fmaxf(sv * gv + bev, 0.f) + fsrc[(size_t)b * 1920 + o * 60 + gg];
                    }
                }
            }
        }
    }
}

// ---- finalize: epT[(b,g)][32] -> inv + normalized eqv [b][c][g] ----
__global__ __launch_bounds__(64) void finalize_t(
    const float* __restrict__ epT, float* __restrict__ e_store,
    float* __restrict__ out_eqv, float* __restrict__ out_inv)
{
    __shared__ float s[1920];
    __shared__ float norms[60];
    __shared__ float invv[32];
    __shared__ float ninv;
    const int b = blockIdx.x, t = threadIdx.x;

    for (int i = t; i < 1920; i += 64) s[i] = epT[(size_t)b * 1920 + i];
    __syncthreads();
    if (t < 60) {
        float a = 0.f;
        #pragma unroll
        for (int c = 0; c < 32; ++c) { float v = s[t * 32 + c]; a += v * v; }
        norms[t] = fmaxf(sqrtf(a), 1e-4f);
    }
    if (t < 32) {
        float a = 0.f;
        for (int g = 0; g < 60; ++g) a += s[g * 32 + t];
        invv[t] = a * (1.f / 60.f);
    }
    __syncthreads();
    if (t == 0) {
        float a = 0.f;
        #pragma unroll
        for (int c = 0; c < 32; ++c) a += invv[c] * invv[c];
        ninv = fmaxf(sqrtf(a), 1e-4f);
    }
    __syncthreads();
    if (t < 32) out_inv[b * 32 + t] = invv[t] / ninv;
    for (int i = t; i < 1920; i += 64) {
        const int g = i >> 5, c = i & 31;
        const float v = s[i] / norms[g];
        const size_t oi = (size_t)b * 1920 + c * 60 + g;
        out_eqv[oi] = v;
        e_store[oi] = v;
    }
}

// ---- des2dr ----
__global__ __launch_bounds__(64) void des2dr_kernel(
    const float* __restrict__ e0, const float* __restrict__ e1,
    const int* __restrict__ permu, int* __restrict__ pre)
{
    __shared__ float s0[1920], s1[1920];
    __shared__ float cor[60];
    __shared__ int sp[3600];
    const int b = blockIdx.x, t = threadIdx.x;

    for (int i = t; i < 1920; i += 64) {
        s0[i] = e0[(size_t)b * 1920 + i];
        s1[i] = e1[(size_t)b * 1920 + i];
    }
    for (int i = t; i < 3600; i += 64) sp[i] = permu[i];
    __syncthreads();

    if (t < 60) {
        float a = 0.f;
        for (int g = 0; g < 60; ++g) {
            const int p = sp[t * 60 + g];
            #pragma unroll 8
            for (int f = 0; f < 32; ++f) a += s0[f * 60 + p] * s1[f * 60 + g];
        }
        cor[t] = a;
    }
    __syncthreads();
    if (t == 0) {
        float best = cor[0]; int bi = 0;
        for (int a = 1; a < 60; ++a) if (cor[a] > best) { best = cor[a]; bi = a; }
        pre[b] = bi;
    }
}

// ---- ability + integer outputs ----
__global__ __launch_bounds__(256) void final_kernel(
    const int* __restrict__ pre, const int* __restrict__ truei,
    float* __restrict__ out)
{
    __shared__ int cnt[256];
    const int t = threadIdx.x;
    cnt[t] = (pre[t] == truei[t]) ? 1 : 0;
    __syncthreads();
    for (int s = 128; s > 0; s >>= 1) {
        if (t < s) cnt[t] += cnt[t + s];
        __syncthreads();
    }
    if (t == 0) out[OFF_AB] = (float)cnt[0] / 256.f;
    out[OFF_TI + t] = (float)truei[t];
    out[OFF_PI + t] = (float)pre[t];
}

// ---------------------------------------------------------------------------
extern "C" void kernel_launch(void* const* d_in, const int* in_sizes, int n_in,
                              void* d_out, int out_size)
{
    const float* feats0 = (const float*)d_in[0];
    const float* feats1 = (const float*)d_in[1];
    const int*   truei  = (const int*)  d_in[2];
    const int*   nei    = (const int*)  d_in[3];
    const int*   permu  = (const int*)  d_in[4];
    const float* W_in = (const float*)d_in[5];  const float* b_in = (const float*)d_in[6];
    const float* W1   = (const float*)d_in[7];  const float* b1   = (const float*)d_in[8];
    const float* g1   = (const float*)d_in[9];  const float* be1  = (const float*)d_in[10];
    const float* W2   = (const float*)d_in[11]; const float* b2   = (const float*)d_in[12];
    const float* g2   = (const float*)d_in[13]; const float* be2  = (const float*)d_in[14];
    const float* Wo   = (const float*)d_in[15]; const float* bo   = (const float*)d_in[16];
    const float* go   = (const float*)d_in[17]; const float* beo  = (const float*)d_in[18];
    float* out = (float*)d_out;

    __nv_bfloat16 *WpI, *Wp1, *Wp2, *WpO, *fP, *dP, *f1P, *d2P;
    float *dT32, *epT, *e0, *e1;
    int* pre;
    cudaGetSymbolAddress((void**)&WpI,  g_WpI);
    cudaGetSymbolAddress((void**)&Wp1,  g_Wp1);
    cudaGetSymbolAddress((void**)&Wp2,  g_Wp2);
    cudaGetSymbolAddress((void**)&WpO,  g_WpO);
    cudaGetSymbolAddress((void**)&fP,   g_fP);
    cudaGetSymbolAddress((void**)&dP,   g_dP);
    cudaGetSymbolAddress((void**)&f1P,  g_f1P);
    cudaGetSymbolAddress((void**)&d2P,  g_d2P);
    cudaGetSymbolAddress((void**)&dT32, g_dT32);
    cudaGetSymbolAddress((void**)&epT,  g_epT);
    cudaGetSymbolAddress((void**)&e0,   g_e0);
    cudaGetSymbolAddress((void**)&e1,   g_e1);
    cudaGetSymbolAddress((void**)&pre,  g_pre);

    cudaFuncSetAttribute(gf_gemm, cudaFuncAttributeMaxDynamicSharedMemorySize, SMEM_DYN);

    cudaMemcpyAsync(out + OFF_F0, feats0, (size_t)491520 * 4, cudaMemcpyDeviceToDevice, 0);
    cudaMemcpyAsync(out + OFF_F1, feats1, (size_t)491520 * 4, cudaMemcpyDeviceToDevice, 0);

    prep_w<<<(256 * 13 * 64) / 256, 256>>>(WpI, W_in, 256, 32, 13);
    prep_w<<<(512 * 52 * 64) / 256, 256>>>(Wp1, W1, 512, 256, 52);
    prep_w<<<(256 * 104 * 64) / 256, 256>>>(Wp2, W2, 256, 512, 104);
    prep_w<<<(128 * 52 * 64) / 256, 256>>>(WpO, Wo, 32, 256, 52);

    prep_feats<<<(NTOT * 64) / 256, 256>>>(fP, feats0);
    prep_feats<<<(NTOT * 64) / 256, 256>>>(fP + (size_t)NTOT * 128, feats1);

    // conv_in: nch=1, O=256 -> mode 0 (dT32 + dP)
    gf_gemm<<<dim3(120, 2), 256, SMEM_DYN>>>(WpI, fP, 1, 13, nei, 0,
        b_in, b_in, b_in, dT32, feats0, feats1, dT32, dP, 4);
    // layer1: nch=4, O=512 -> mode 1 (f1P)
    gf_gemm<<<dim3(120, 4), 256, SMEM_DYN>>>(Wp1, dP, 4, 52, nei, 1,
        b1, g1, be1, dT32, feats0, feats1, dT32, f1P, 8);
    // layer2: nch=8, O=256 -> mode 2 (residual dT32 -> d2P)
    gf_gemm<<<dim3(120, 2), 256, SMEM_DYN>>>(Wp2, f1P, 8, 104, nei, 2,
        b2, g2, be2, dT32, feats0, feats1, dT32, d2P, 4);
    // conv_out: nch=4, O=32(pad128) -> mode 3 (+feats -> epT)
    gf_gemm<<<dim3(120, 1), 256, SMEM_DYN>>>(WpO, d2P, 4, 52, nei, 3,
        bo, go, beo, dT32, feats0, feats1, epT, dP, 4);

    finalize_t<<<BATCH, 64>>>(epT, e0, out + OFF_E0, out + OFF_I0);
    finalize_t<<<BATCH, 64>>>(epT + (size_t)NTOT * 32, e1, out + OFF_E1, out + OFF_I1);

    des2dr_kernel<<<BATCH, 64>>>(e0, e1, permu, pre);
    final_kernel<<<1, 256>>>(pre, truei, out);
}

// round 14
// speedup vs baseline: 2.2125x; 1.4287x over previous
#include <cuda_runtime.h>
#include <cuda_fp16.h>
#include <math.h>
#include <stdint.h>

#define BATCH 256
#define GSZ   60
#define KSZ   13
#define NTOT  (BATCH * GSZ)    // 15360 per net
#define NTOT2 (2 * NTOT)       // 30720 both nets

#define OFF_F0 0
#define OFF_F1 491520
#define OFF_E0 983040
#define OFF_E1 1474560
#define OFF_I0 1966080
#define OFF_I1 1974272
#define OFF_AB 1982464
#define OFF_TI 1982465
#define OFF_PI 1982721

// ---------------------------------------------------------------------------
// Device scratch.
// Weights: Wp[o][s][hi64 | lo64] fp16, s = j*13+k (chunk-major), 2-plane split.
// Acts:    actP[n][j][64] fp16 single plane, n = net*15360 + b*60 + g.
// ---------------------------------------------------------------------------
__device__ __half g_WpI[256 * 13 * 128];
__device__ __half g_Wp1[512 * 52 * 128];
__device__ __half g_Wp2[256 * 104 * 128];
__device__ __half g_WpO[128 * 52 * 128];
__device__ __half g_fP [NTOT2 * 1 * 64];
__device__ __half g_dP [NTOT2 * 4 * 64];
__device__ __half g_f1P[NTOT2 * 8 * 64];
__device__ __half g_d2P[NTOT2 * 4 * 64];
__device__ float g_dT32[NTOT2 * 256];
__device__ float g_epT [NTOT2 * 32];
__device__ float g_e0  [BATCH * 32 * GSZ];
__device__ float g_e1  [BATCH * 32 * GSZ];
__device__ int   g_pre [BATCH];

// ---- helpers ----
__device__ __forceinline__ uint32_t smem_u32(const void* p) {
    uint32_t a;
    asm("{ .reg .u64 t; cvta.to.shared.u64 t, %1; cvt.u32.u64 %0, t; }" : "=r"(a) : "l"(p));
    return a;
}
#define SWZ(x) ((x) ^ (((x) >> 3) & 0x70))

__device__ __forceinline__ void cpasync16(uint32_t dst, const void* src) {
    asm volatile("cp.async.ca.shared.global [%0], [%1], 16;" :: "r"(dst), "l"(src) : "memory");
}
__device__ __forceinline__ void cp_commit() {
    asm volatile("cp.async.commit_group;" ::: "memory");
}
__device__ __forceinline__ void cp_wait2() {
    asm volatile("cp.async.wait_group 2;" ::: "memory");
}
__device__ __forceinline__ void ldsm4(uint32_t* r, uint32_t a) {
    asm volatile("ldmatrix.sync.aligned.m8n8.x4.shared.b16 {%0,%1,%2,%3}, [%4];"
                 : "=r"(r[0]), "=r"(r[1]), "=r"(r[2]), "=r"(r[3]) : "r"(a));
}
__device__ __forceinline__ void ldsm2(uint32_t* r, uint32_t a) {
    asm volatile("ldmatrix.sync.aligned.m8n8.x2.shared.b16 {%0,%1}, [%2];"
                 : "=r"(r[0]), "=r"(r[1]) : "r"(a));
}
__device__ __forceinline__ void mma_fp16(float* d, const uint32_t* a, const uint32_t* b) {
    asm volatile(
        "mma.sync.aligned.m16n8k16.row.col.f32.f16.f16.f32 "
        "{%0,%1,%2,%3},{%4,%5,%6,%7},{%8,%9},{%0,%1,%2,%3};"
        : "+f"(d[0]), "+f"(d[1]), "+f"(d[2]), "+f"(d[3])
        : "r"(a[0]), "r"(a[1]), "r"(a[2]), "r"(a[3]), "r"(b[0]), "r"(b[1]));
}
__device__ __forceinline__ void split_h(float v, __half& h, __half& l) {
    h = __float2half(v);
    l = __float2half(v - __half2float(h));
}

// ---- prep: W[o][cr][k] -> Wp[o][s][hi64|lo64], s=j*13+k ----
__global__ __launch_bounds__(256) void prep_w(
    __half* __restrict__ dst, const float* __restrict__ W,
    int Oreal, int Creal, int nstages)
{
    int idx = blockIdx.x * 256 + threadIdx.x;
    int c = idx & 63;
    int s = (idx >> 6) % nstages;
    int o = idx / (64 * nstages);
    int k = s % 13, j = s / 13;
    int cr = j * 64 + c;
    float v = 0.f;
    if (o < Oreal && cr < Creal) v = W[((size_t)o * Creal + cr) * 13 + k];
    __half h, l; split_h(v, h, l);
    size_t base = ((size_t)o * nstages + s) * 128;
    dst[base + c] = h;
    dst[base + 64 + c] = l;
}

// ---- prep: feats[b][c][g] -> dst[n][64] single fp16 plane ----
__global__ __launch_bounds__(256) void prep_feats(
    __half* __restrict__ dst, const float* __restrict__ f)
{
    int idx = blockIdx.x * 256 + threadIdx.x;   // < 15360*64
    int c = idx & 63;
    int n = idx >> 6;
    int b = n / 60, g = n - b * 60;
    float v = (c < 32) ? f[(size_t)b * 1920 + c * 60 + g] : 0.f;
    dst[(size_t)n * 64 + c] = __float2half(v);
}

// ---------------------------------------------------------------------------
// Gather-fused GEMM, 2-pass fp16 (A hi/lo split, B single plane).
// CTA tile M=128 x N=256; 8 warps (2M x 4N), warp tile 64x64.
// Stage = one (chunk j, k): A 32KB (2 planes) + B 32KB (1 plane), SW128,
// conflict-free ldmatrix. 3-deep cp.async ring, one group per stage.
// ---------------------------------------------------------------------------
#define OFF_STG  16384
#define STG_SZ   65536
#define NSTAGE   3
#define SMEM_DYN (OFF_STG + NSTAGE * STG_SZ)   // 212992

__global__ __launch_bounds__(256, 1) void gf_gemm(
    const __half* __restrict__ Wp, const __half* __restrict__ actP,
    int nch, int nstages, const int* __restrict__ nei, int mode,
    const float* __restrict__ bias, const float* __restrict__ gamma,
    const float* __restrict__ beta, const float* __restrict__ dres,
    const float* __restrict__ feats0, const float* __restrict__ feats1,
    float* __restrict__ out32, __half* __restrict__ actOut, int nchO)
{
    extern __shared__ __align__(1024) char smem[];
    int* lut = (int*)smem;                    // [13][256] absolute act row index
    const uint32_t su = smem_u32(smem);
    const int tid = threadIdx.x;
    const int warp = tid >> 5, lane = tid & 31;
    const int n0 = blockIdx.x * 256;          // global position (both nets)
    const int m0 = blockIdx.y * 128;

    {
        const int n = n0 + tid;
        const int net = n / NTOT;
        const int nw = n - net * NTOT;
        const int b = nw / 60, g = nw - b * 60;
        #pragma unroll
        for (int k = 0; k < KSZ; ++k)
            lut[k * 256 + tid] = net * NTOT + b * 60 + nei[g * KSZ + k];
    }
    __syncthreads();

    const int arow_l = tid >> 1;       // 0..127
    const int ahalf  = tid & 1;        // 0: hi plane, 1: lo plane

    auto load_stage = [&](int s) {
        const uint32_t bufs = su + OFF_STG + (uint32_t)(s % NSTAGE) * STG_SZ;
        // A: 128 rows x 128B per plane (2 planes: hi @0, lo @16384)
        {
            const char* src = (const char*)(Wp + ((size_t)(m0 + arow_l) * nstages + s) * 128)
                              + ahalf * 128;
            const uint32_t dst = bufs + (uint32_t)ahalf * 16384;
            #pragma unroll
            for (int c = 0; c < 8; ++c)
                cpasync16(dst + SWZ((uint32_t)(arow_l * 128 + c * 16)), src + c * 16);
        }
        // B: 256 gathered rows x 128B, single plane @32768
        {
            const int k = s % 13, j = s / 13;
            const int sr = lut[k * 256 + tid];
            const char* src = (const char*)(actP + ((size_t)sr * nch + j) * 64);
            const uint32_t dst = bufs + 32768;
            #pragma unroll
            for (int c = 0; c < 8; ++c)
                cpasync16(dst + SWZ((uint32_t)(tid * 128 + c * 16)), src + c * 16);
        }
    };

    // prologue: fill the 3-deep ring
    load_stage(0); cp_commit();
    if (1 < nstages) load_stage(1); cp_commit();
    if (2 < nstages) load_stage(2); cp_commit();

    const int wm = warp >> 2, wn = warp & 3;
    float acc[4][8][4] = {};

    const uint32_t arow = (uint32_t)(wm * 64 + (lane & 15));
    const uint32_t acolx = (uint32_t)((lane >> 4) * 16);
    const uint32_t brow = (uint32_t)(wn * 64 + (lane & 7));
    const uint32_t bcolx = (uint32_t)(((lane >> 3) & 1) * 16);

    for (int s = 0; s < nstages; ++s) {
        cp_wait2();
        __syncthreads();
        const uint32_t bufs = su + OFF_STG + (uint32_t)(s % NSTAGE) * STG_SZ;
        const uint32_t Ah = bufs, Al = bufs + 16384, Bp = bufs + 32768;

        #pragma unroll
        for (int ks = 0; ks < 4; ++ks) {
            const uint32_t kb = ks * 32;
            uint32_t ah[4][4], al[4][4], bp[8][2];
            #pragma unroll
            for (int mt = 0; mt < 4; ++mt) {
                const uint32_t off = SWZ((arow + mt * 16) * 128 + kb + acolx);
                ldsm4(ah[mt], Ah + off);
                ldsm4(al[mt], Al + off);
            }
            #pragma unroll
            for (int nt = 0; nt < 8; ++nt) {
                const uint32_t off = SWZ((brow + nt * 8) * 128 + kb + bcolx);
                ldsm2(bp[nt], Bp + off);
            }
            #pragma unroll
            for (int mt = 0; mt < 4; ++mt)
                #pragma unroll
                for (int nt = 0; nt < 8; ++nt) {
                    mma_fp16(acc[mt][nt], ah[mt], bp[nt]);
                    mma_fp16(acc[mt][nt], al[mt], bp[nt]);
                }
        }
        __syncthreads();
        if (s + NSTAGE < nstages) load_stage(s + NSTAGE);
        cp_commit();
    }

    // ---- epilogue ----
    const int g4 = lane >> 2, t4 = lane & 3;
    #pragma unroll
    for (int mt = 0; mt < 4; ++mt) {
        #pragma unroll
        for (int dr = 0; dr < 2; ++dr) {
            const int o = m0 + wm * 64 + mt * 16 + g4 + dr * 8;
            if (mode == 3 && o >= 32) continue;
            const float bv = bias[o];
            float gv = 0.f, bev = 0.f;
            if (mode != 0) { gv = gamma[o]; bev = beta[o]; }
            const int jo = o >> 6, co = o & 63;
            #pragma unroll
            for (int nt = 0; nt < 8; ++nt) {
                #pragma unroll
                for (int dn = 0; dn < 2; ++dn) {
                    const float sv = acc[mt][nt][dr * 2 + dn] + bv;
                    const int n = n0 + wn * 64 + nt * 8 + t4 * 2 + dn;
                    if (mode == 0) {
                        out32[(size_t)n * 256 + o] = sv;
                        actOut[((size_t)n * nchO + jo) * 64 + co] = __float2half(sv);
                    } else if (mode == 1) {
                        const float v = fmaxf(sv * gv + bev, 0.f);
                        actOut[((size_t)n * nchO + jo) * 64 + co] = __float2half(v);
                    } else if (mode == 2) {
                        const float v = fmaxf(sv * gv + bev, 0.f) + dres[(size_t)n * 256 + o];
                        actOut[((size_t)n * nchO + jo) * 64 + co] = __float2half(v);
                    } else {
                        const int netl = n / NTOT;
                        const int nw = n - netl * NTOT;
                        const int b = nw / 60, gg = nw - b * 60;
                        const float* fsrc = netl ? feats1 : feats0;
                        out32[(size_t)n * 32 + o] =
                            fmaxf(sv * gv + bev, 0.f) + fsrc[(size_t)b * 1920 + o * 60 + gg];
                    }
                }
            }
        }
    }
}

// ---- finalize: epT[(b,g)][32] -> inv + normalized eqv [b][c][g] ----
__global__ __launch_bounds__(64) void finalize_t(
    const float* __restrict__ epT, float* __restrict__ e_store,
    float* __restrict__ out_eqv, float* __restrict__ out_inv)
{
    __shared__ float s[1920];
    __shared__ float norms[60];
    __shared__ float invv[32];
    __shared__ float ninv;
    const int b = blockIdx.x, t = threadIdx.x;

    for (int i = t; i < 1920; i += 64) s[i] = epT[(size_t)b * 1920 + i];
    __syncthreads();
    if (t < 60) {
        float a = 0.f;
        #pragma unroll
        for (int c = 0; c < 32; ++c) { float v = s[t * 32 + c]; a += v * v; }
        norms[t] = fmaxf(sqrtf(a), 1e-4f);
    }
    if (t < 32) {
        float a = 0.f;
        for (int g = 0; g < 60; ++g) a += s[g * 32 + t];
        invv[t] = a * (1.f / 60.f);
    }
    __syncthreads();
    if (t == 0) {
        float a = 0.f;
        #pragma unroll
        for (int c = 0; c < 32; ++c) a += invv[c] * invv[c];
        ninv = fmaxf(sqrtf(a), 1e-4f);
    }
    __syncthreads();
    if (t < 32) out_inv[b * 32 + t] = invv[t] / ninv;
    for (int i = t; i < 1920; i += 64) {
        const int g = i >> 5, c = i & 31;
        const float v = s[i] / norms[g];
        const size_t oi = (size_t)b * 1920 + c * 60 + g;
        out_eqv[oi] = v;
        e_store[oi] = v;
    }
}

// ---- des2dr ----
__global__ __launch_bounds__(64) void des2dr_kernel(
    const float* __restrict__ e0, const float* __restrict__ e1,
    const int* __restrict__ permu, int* __restrict__ pre)
{
    __shared__ float s0[1920], s1[1920];
    __shared__ float cor[60];
    __shared__ int sp[3600];
    const int b = blockIdx.x, t = threadIdx.x;

    for (int i = t; i < 1920; i += 64) {
        s0[i] = e0[(size_t)b * 1920 + i];
        s1[i] = e1[(size_t)b * 1920 + i];
    }
    for (int i = t; i < 3600; i += 64) sp[i] = permu[i];
    __syncthreads();

    if (t < 60) {
        float a = 0.f;
        for (int g = 0; g < 60; ++g) {
            const int p = sp[t * 60 + g];
            #pragma unroll 8
            for (int f = 0; f < 32; ++f) a += s0[f * 60 + p] * s1[f * 60 + g];
        }
        cor[t] = a;
    }
    __syncthreads();
    if (t == 0) {
        float best = cor[0]; int bi = 0;
        for (int a = 1; a < 60; ++a) if (cor[a] > best) { best = cor[a]; bi = a; }
        pre[b] = bi;
    }
}

// ---- ability + integer outputs ----
__global__ __launch_bounds__(256) void final_kernel(
    const int* __restrict__ pre, const int* __restrict__ truei,
    float* __restrict__ out)
{
    __shared__ int cnt[256];
    const int t = threadIdx.x;
    cnt[t] = (pre[t] == truei[t]) ? 1 : 0;
    __syncthreads();
    for (int s = 128; s > 0; s >>= 1) {
        if (t < s) cnt[t] += cnt[t + s];
        __syncthreads();
    }
    if (t == 0) out[OFF_AB] = (float)cnt[0] / 256.f;
    out[OFF_TI + t] = (float)truei[t];
    out[OFF_PI + t] = (float)pre[t];
}

// ---------------------------------------------------------------------------
extern "C" void kernel_launch(void* const* d_in, const int* in_sizes, int n_in,
                              void* d_out, int out_size)
{
    const float* feats0 = (const float*)d_in[0];
    const float* feats1 = (const float*)d_in[1];
    const int*   truei  = (const int*)  d_in[2];
    const int*   nei    = (const int*)  d_in[3];
    const int*   permu  = (const int*)  d_in[4];
    const float* W_in = (const float*)d_in[5];  const float* b_in = (const float*)d_in[6];
    const float* W1   = (const float*)d_in[7];  const float* b1   = (const float*)d_in[8];
    const float* g1   = (const float*)d_in[9];  const float* be1  = (const float*)d_in[10];
    const float* W2   = (const float*)d_in[11]; const float* b2   = (const float*)d_in[12];
    const float* g2   = (const float*)d_in[13]; const float* be2  = (const float*)d_in[14];
    const float* Wo   = (const float*)d_in[15]; const float* bo   = (const float*)d_in[16];
    const float* go   = (const float*)d_in[17]; const float* beo  = (const float*)d_in[18];
    float* out = (float*)d_out;

    __half *WpI, *Wp1, *Wp2, *WpO, *fP, *dP, *f1P, *d2P;
    float *dT32, *epT, *e0, *e1;
    int* pre;
    cudaGetSymbolAddress((void**)&WpI,  g_WpI);
    cudaGetSymbolAddress((void**)&Wp1,  g_Wp1);
    cudaGetSymbolAddress((void**)&Wp2,  g_Wp2);
    cudaGetSymbolAddress((void**)&WpO,  g_WpO);
    cudaGetSymbolAddress((void**)&fP,   g_fP);
    cudaGetSymbolAddress((void**)&dP,   g_dP);
    cudaGetSymbolAddress((void**)&f1P,  g_f1P);
    cudaGetSymbolAddress((void**)&d2P,  g_d2P);
    cudaGetSymbolAddress((void**)&dT32, g_dT32);
    cudaGetSymbolAddress((void**)&epT,  g_epT);
    cudaGetSymbolAddress((void**)&e0,   g_e0);
    cudaGetSymbolAddress((void**)&e1,   g_e1);
    cudaGetSymbolAddress((void**)&pre,  g_pre);

    cudaFuncSetAttribute(gf_gemm, cudaFuncAttributeMaxDynamicSharedMemorySize, SMEM_DYN);

    cudaMemcpyAsync(out + OFF_F0, feats0, (size_t)491520 * 4, cudaMemcpyDeviceToDevice, 0);
    cudaMemcpyAsync(out + OFF_F1, feats1, (size_t)491520 * 4, cudaMemcpyDeviceToDevice, 0);

    prep_w<<<(256 * 13 * 64) / 256, 256>>>(WpI, W_in, 256, 32, 13);
    prep_w<<<(512 * 52 * 64) / 256, 256>>>(Wp1, W1, 512, 256, 52);
    prep_w<<<(256 * 104 * 64) / 256, 256>>>(Wp2, W2, 256, 512, 104);
    prep_w<<<(128 * 52 * 64) / 256, 256>>>(WpO, Wo, 32, 256, 52);

    prep_feats<<<(NTOT * 64) / 256, 256>>>(fP, feats0);
    prep_feats<<<(NTOT * 64) / 256, 256>>>(fP + (size_t)NTOT * 64, feats1);

    // conv_in: nch=1, O=256 -> mode 0 (dT32 + dP)
    gf_gemm<<<dim3(120, 2), 256, SMEM_DYN>>>(WpI, fP, 1, 13, nei, 0,
        b_in, b_in, b_in, dT32, feats0, feats1, dT32, dP, 4);
    // layer1: nch=4, O=512 -> mode 1 (f1P)
    gf_gemm<<<dim3(120, 4), 256, SMEM_DYN>>>(Wp1, dP, 4, 52, nei, 1,
        b1, g1, be1, dT32, feats0, feats1, dT32, f1P, 8);
    // layer2: nch=8, O=256 -> mode 2 (residual dT32 -> d2P)
    gf_gemm<<<dim3(120, 2), 256, SMEM_DYN>>>(Wp2, f1P, 8, 104, nei, 2,
        b2, g2, be2, dT32, feats0, feats1, dT32, d2P, 4);
    // conv_out: nch=4, O=32(pad128) -> mode 3 (+feats -> epT)
    gf_gemm<<<dim3(120, 1), 256, SMEM_DYN>>>(WpO, d2P, 4, 52, nei, 3,
        bo, go, beo, dT32, feats0, feats1, epT, dP, 4);

    finalize_t<<<BATCH, 64>>>(epT, e0, out + OFF_E0, out + OFF_I0);
    finalize_t<<<BATCH, 64>>>(epT + (size_t)NTOT * 32, e1, out + OFF_E1, out + OFF_I1);

    des2dr_kernel<<<BATCH, 64>>>(e0, e1, permu, pre);
    final_kernel<<<1, 256>>>(pre, truei, out);
}

// round 16
// speedup vs baseline: 4.1108x; 1.8580x over previous
#include <cuda_runtime.h>
#include <cuda_fp16.h>
#include <math.h>
#include <stdint.h>

#define BATCH 256
#define GSZ   60
#define KSZ   13
#define NTOT  (BATCH * GSZ)    // 15360 per net
#define NTOT2 (2 * NTOT)       // 30720 both nets

#define OFF_F0 0
#define OFF_F1 491520
#define OFF_E0 983040
#define OFF_E1 1474560
#define OFF_I0 1966080
#define OFF_I1 1974272
#define OFF_AB 1982464
#define OFF_TI 1982465
#define OFF_PI 1982721

// ---------------------------------------------------------------------------
// Device scratch.
// Weights: Wp[o][s][64] fp16 single plane, s = j*13+k (chunk-major).
// Acts:    actP[n][j][64] fp16 single plane, n = net*15360 + b*60 + g.
// ---------------------------------------------------------------------------
__device__ __half g_WpI[256 * 13 * 64];
__device__ __half g_Wp1[512 * 52 * 64];
__device__ __half g_Wp2[256 * 104 * 64];
__device__ __half g_WpO[128 * 52 * 64];
__device__ __half g_fP [NTOT2 * 1 * 64];
__device__ __half g_dP [NTOT2 * 4 * 64];
__device__ __half g_f1P[NTOT2 * 8 * 64];
__device__ __half g_d2P[NTOT2 * 4 * 64];
__device__ float g_dT32[NTOT2 * 256];
__device__ float g_epT [NTOT2 * 32];
__device__ float g_e0  [BATCH * 32 * GSZ];
__device__ float g_e1  [BATCH * 32 * GSZ];
__device__ int   g_pre [BATCH];

// ---- helpers ----
__device__ __forceinline__ uint32_t smem_u32(const void* p) {
    uint32_t a;
    asm("{ .reg .u64 t; cvta.to.shared.u64 t, %1; cvt.u32.u64 %0, t; }" : "=r"(a) : "l"(p));
    return a;
}
#define SWZ(x) ((x) ^ (((x) >> 3) & 0x70))

__device__ __forceinline__ void cpasync16(uint32_t dst, const void* src) {
    asm volatile("cp.async.ca.shared.global [%0], [%1], 16;" :: "r"(dst), "l"(src) : "memory");
}
__device__ __forceinline__ void cp_commit() {
    asm volatile("cp.async.commit_group;" ::: "memory");
}
__device__ __forceinline__ void cp_wait3() {
    asm volatile("cp.async.wait_group 3;" ::: "memory");
}
__device__ __forceinline__ void ldsm4(uint32_t* r, uint32_t a) {
    asm volatile("ldmatrix.sync.aligned.m8n8.x4.shared.b16 {%0,%1,%2,%3}, [%4];"
                 : "=r"(r[0]), "=r"(r[1]), "=r"(r[2]), "=r"(r[3]) : "r"(a));
}
__device__ __forceinline__ void ldsm2(uint32_t* r, uint32_t a) {
    asm volatile("ldmatrix.sync.aligned.m8n8.x2.shared.b16 {%0,%1}, [%2];"
                 : "=r"(r[0]), "=r"(r[1]) : "r"(a));
}
__device__ __forceinline__ void mma_fp16(float* d, const uint32_t* a, const uint32_t* b) {
    asm volatile(
        "mma.sync.aligned.m16n8k16.row.col.f32.f16.f16.f32 "
        "{%0,%1,%2,%3},{%4,%5,%6,%7},{%8,%9},{%0,%1,%2,%3};"
        : "+f"(d[0]), "+f"(d[1]), "+f"(d[2]), "+f"(d[3])
        : "r"(a[0]), "r"(a[1]), "r"(a[2]), "r"(a[3]), "r"(b[0]), "r"(b[1]));
}

// ---- prep: W[o][cr][k] -> Wp[o][s][64] fp16, s=j*13+k ----
__global__ __launch_bounds__(256) void prep_w(
    __half* __restrict__ dst, const float* __restrict__ W,
    int Oreal, int Creal, int nstages)
{
    int idx = blockIdx.x * 256 + threadIdx.x;
    int c = idx & 63;
    int s = (idx >> 6) % nstages;
    int o = idx / (64 * nstages);
    int k = s % 13, j = s / 13;
    int cr = j * 64 + c;
    float v = 0.f;
    if (o < Oreal && cr < Creal) v = W[((size_t)o * Creal + cr) * 13 + k];
    dst[((size_t)o * nstages + s) * 64 + c] = __float2half(v);
}

// ---- prep: feats[b][c][g] -> dst[n][64] single fp16 plane ----
__global__ __launch_bounds__(256) void prep_feats(
    __half* __restrict__ dst, const float* __restrict__ f)
{
    int idx = blockIdx.x * 256 + threadIdx.x;   // < 15360*64
    int c = idx & 63;
    int n = idx >> 6;
    int b = n / 60, g = n - b * 60;
    float v = (c < 32) ? f[(size_t)b * 1920 + c * 60 + g] : 0.f;
    dst[(size_t)n * 64 + c] = __float2half(v);
}

// ---------------------------------------------------------------------------
// Gather-fused GEMM, single-pass fp16 (A and B single plane).
// CTA tile M=128 x N=256; 8 warps (2M x 4N), warp tile 64x64.
// Stage = one (chunk j, k): A 16KB + B 32KB, SW128, conflict-free ldmatrix.
// 4-deep cp.async ring, one commit group per stage, wait_group 3.
// ---------------------------------------------------------------------------
#define OFF_STG  16384
#define STG_SZ   49152
#define NSTAGE   4
#define SMEM_DYN (OFF_STG + NSTAGE * STG_SZ)   // 212992

__global__ __launch_bounds__(256, 1) void gf_gemm(
    const __half* __restrict__ Wp, const __half* __restrict__ actP,
    int nch, int nstages, const int* __restrict__ nei, int mode,
    const float* __restrict__ bias, const float* __restrict__ gamma,
    const float* __restrict__ beta, const float* __restrict__ dres,
    const float* __restrict__ feats0, const float* __restrict__ feats1,
    float* __restrict__ out32, __half* __restrict__ actOut, int nchO)
{
    extern __shared__ __align__(1024) char smem[];
    int* lut = (int*)smem;                    // [13][256] absolute act row index
    const uint32_t su = smem_u32(smem);
    const int tid = threadIdx.x;
    const int warp = tid >> 5, lane = tid & 31;
    const int n0 = blockIdx.x * 256;          // global position (both nets)
    const int m0 = blockIdx.y * 128;

    {
        const int n = n0 + tid;
        const int net = n / NTOT;
        const int nw = n - net * NTOT;
        const int b = nw / 60, g = nw - b * 60;
        #pragma unroll
        for (int k = 0; k < KSZ; ++k)
            lut[k * 256 + tid] = net * NTOT + b * 60 + nei[g * KSZ + k];
    }
    __syncthreads();

    const int arow_l = tid >> 1;       // 0..127
    const int achnk  = (tid & 1) * 4;  // chunk base 0 or 4

    auto load_stage = [&](int s) {
        const uint32_t bufs = su + OFF_STG + (uint32_t)(s % NSTAGE) * STG_SZ;
        // A: 128 rows x 128B single plane @0 (1024 cp.async over 256 thr)
        {
            const char* src = (const char*)(Wp + ((size_t)(m0 + arow_l) * nstages + s) * 64)
                              + achnk * 16;
            #pragma unroll
            for (int c = 0; c < 4; ++c)
                cpasync16(bufs + SWZ((uint32_t)(arow_l * 128 + (achnk + c) * 16)),
                          src + c * 16);
        }
        // B: 256 gathered rows x 128B single plane @16384
        {
            const int k = s % 13, j = s / 13;
            const int sr = lut[k * 256 + tid];
            const char* src = (const char*)(actP + ((size_t)sr * nch + j) * 64);
            const uint32_t dst = bufs + 16384;
            #pragma unroll
            for (int c = 0; c < 8; ++c)
                cpasync16(dst + SWZ((uint32_t)(tid * 128 + c * 16)), src + c * 16);
        }
    };

    // prologue: fill the 4-deep ring
    #pragma unroll
    for (int s = 0; s < NSTAGE; ++s) {
        if (s < nstages) load_stage(s);
        cp_commit();
    }

    const int wm = warp >> 2, wn = warp & 3;
    float acc[4][8][4] = {};

    const uint32_t arow = (uint32_t)(wm * 64 + (lane & 15));
    const uint32_t acolx = (uint32_t)((lane >> 4) * 16);
    const uint32_t brow = (uint32_t)(wn * 64 + (lane & 7));
    const uint32_t bcolx = (uint32_t)(((lane >> 3) & 1) * 16);

    for (int s = 0; s < nstages; ++s) {
        cp_wait3();
        __syncthreads();
        const uint32_t bufs = su + OFF_STG + (uint32_t)(s % NSTAGE) * STG_SZ;
        const uint32_t Ap = bufs, Bp = bufs + 16384;

        #pragma unroll
        for (int ks = 0; ks < 4; ++ks) {
            const uint32_t kb = ks * 32;
            uint32_t ap[4][4], bp[8][2];
            #pragma unroll
            for (int mt = 0; mt < 4; ++mt) {
                const uint32_t off = SWZ((arow + mt * 16) * 128 + kb + acolx);
                ldsm4(ap[mt], Ap + off);
            }
            #pragma unroll
            for (int nt = 0; nt < 8; ++nt) {
                const uint32_t off = SWZ((brow + nt * 8) * 128 + kb + bcolx);
                ldsm2(bp[nt], Bp + off);
            }
            #pragma unroll
            for (int mt = 0; mt < 4; ++mt)
                #pragma unroll
                for (int nt = 0; nt < 8; ++nt)
                    mma_fp16(acc[mt][nt], ap[mt], bp[nt]);
        }
        __syncthreads();
        if (s + NSTAGE < nstages) load_stage(s + NSTAGE);
        cp_commit();
    }

    // ---- epilogue ----
    const int g4 = lane >> 2, t4 = lane & 3;
    #pragma unroll
    for (int mt = 0; mt < 4; ++mt) {
        #pragma unroll
        for (int dr = 0; dr < 2; ++dr) {
            const int o = m0 + wm * 64 + mt * 16 + g4 + dr * 8;
            if (mode == 3 && o >= 32) continue;
            const float bv = bias[o];
            float gv = 0.f, bev = 0.f;
            if (mode != 0) { gv = gamma[o]; bev = beta[o]; }
            const int jo = o >> 6, co = o & 63;
            #pragma unroll
            for (int nt = 0; nt < 8; ++nt) {
                #pragma unroll
                for (int dn = 0; dn < 2; ++dn) {
                    const float sv = acc[mt][nt][dr * 2 + dn] + bv;
                    const int n = n0 + wn * 64 + nt * 8 + t4 * 2 + dn;
                    if (mode == 0) {
                        out32[(size_t)n * 256 + o] = sv;
                        actOut[((size_t)n * nchO + jo) * 64 + co] = __float2half(sv);
                    } else if (mode == 1) {
                        const float v = fmaxf(sv * gv + bev, 0.f);
                        actOut[((size_t)n * nchO + jo) * 64 + co] = __float2half(v);
                    } else if (mode == 2) {
                        const float v = fmaxf(sv * gv + bev, 0.f) + dres[(size_t)n * 256 + o];
                        actOut[((size_t)n * nchO + jo) * 64 + co] = __float2half(v);
                    } else {
                        const int netl = n / NTOT;
                        const int nw = n - netl * NTOT;
                        const int b = nw / 60, gg = nw - b * 60;
                        const float* fsrc = netl ? feats1 : feats0;
                        out32[(size_t)n * 32 + o] =
                            fmaxf(sv * gv + bev, 0.f) + fsrc[(size_t)b * 1920 + o * 60 + gg];
                    }
                }
            }
        }
    }
}

// ---- finalize: epT[(b,g)][32] -> inv + normalized eqv [b][c][g] ----
__global__ __launch_bounds__(64) void finalize_t(
    const float* __restrict__ epT, float* __restrict__ e_store,
    float* __restrict__ out_eqv, float* __restrict__ out_inv)
{
    __shared__ float s[1920];
    __shared__ float norms[60];
    __shared__ float invv[32];
    __shared__ float ninv;
    const int b = blockIdx.x, t = threadIdx.x;

    for (int i = t; i < 1920; i += 64) s[i] = epT[(size_t)b * 1920 + i];
    __syncthreads();
    if (t < 60) {
        float a = 0.f;
        #pragma unroll
        for (int c = 0; c < 32; ++c) { float v = s[t * 32 + c]; a += v * v; }
        norms[t] = fmaxf(sqrtf(a), 1e-4f);
    }
    if (t < 32) {
        float a = 0.f;
        for (int g = 0; g < 60; ++g) a += s[g * 32 + t];
        invv[t] = a * (1.f / 60.f);
    }
    __syncthreads();
    if (t == 0) {
        float a = 0.f;
        #pragma unroll
        for (int c = 0; c < 32; ++c) a += invv[c] * invv[c];
        ninv = fmaxf(sqrtf(a), 1e-4f);
    }
    __syncthreads();
    if (t < 32) out_inv[b * 32 + t] = invv[t] / ninv;
    for (int i = t; i < 1920; i += 64) {
        const int g = i >> 5, c = i & 31;
        const float v = s[i] / norms[g];
        const size_t oi = (size_t)b * 1920 + c * 60 + g;
        out_eqv[oi] = v;
        e_store[oi] = v;
    }
}

// ---- des2dr ----
__global__ __launch_bounds__(64) void des2dr_kernel(
    const float* __restrict__ e0, const float* __restrict__ e1,
    const int* __restrict__ permu, int* __restrict__ pre)
{
    __shared__ float s0[1920], s1[1920];
    __shared__ float cor[60];
    __shared__ int sp[3600];
    const int b = blockIdx.x, t = threadIdx.x;

    for (int i = t; i < 1920; i += 64) {
        s0[i] = e0[(size_t)b * 1920 + i];
        s1[i] = e1[(size_t)b * 1920 + i];
    }
    for (int i = t; i < 3600; i += 64) sp[i] = permu[i];
    __syncthreads();

    if (t < 60) {
        float a = 0.f;
        for (int g = 0; g < 60; ++g) {
            const int p = sp[t * 60 + g];
            #pragma unroll 8
            for (int f = 0; f < 32; ++f) a += s0[f * 60 + p] * s1[f * 60 + g];
        }
        cor[t] = a;
    }
    __syncthreads();
    if (t == 0) {
        float best = cor[0]; int bi = 0;
        for (int a = 1; a < 60; ++a) if (cor[a] > best) { best = cor[a]; bi = a; }
        pre[b] = bi;
    }
}

// ---- ability + integer outputs ----
__global__ __launch_bounds__(256) void final_kernel(
    const int* __restrict__ pre, const int* __restrict__ truei,
    float* __restrict__ out)
{
    __shared__ int cnt[256];
    const int t = threadIdx.x;
    cnt[t] = (pre[t] == truei[t]) ? 1 : 0;
    __syncthreads();
    for (int s = 128; s > 0; s >>= 1) {
        if (t < s) cnt[t] += cnt[t + s];
        __syncthreads();
    }
    if (t == 0) out[OFF_AB] = (float)cnt[0] / 256.f;
    out[OFF_TI + t] = (float)truei[t];
    out[OFF_PI + t] = (float)pre[t];
}

// ---------------------------------------------------------------------------
extern "C" void kernel_launch(void* const* d_in, const int* in_sizes, int n_in,
                              void* d_out, int out_size)
{
    const float* feats0 = (const float*)d_in[0];
    const float* feats1 = (const float*)d_in[1];
    const int*   truei  = (const int*)  d_in[2];
    const int*   nei    = (const int*)  d_in[3];
    const int*   permu  = (const int*)  d_in[4];
    const float* W_in = (const float*)d_in[5];  const float* b_in = (const float*)d_in[6];
    const float* W1   = (const float*)d_in[7];  const float* b1   = (const float*)d_in[8];
    const float* g1   = (const float*)d_in[9];  const float* be1  = (const float*)d_in[10];
    const float* W2   = (const float*)d_in[11]; const float* b2   = (const float*)d_in[12];
    const float* g2   = (const float*)d_in[13]; const float* be2  = (const float*)d_in[14];
    const float* Wo   = (const float*)d_in[15]; const float* bo   = (const float*)d_in[16];
    const float* go   = (const float*)d_in[17]; const float* beo  = (const float*)d_in[18];
    float* out = (float*)d_out;

    __half *WpI, *Wp1, *Wp2, *WpO, *fP, *dP, *f1P, *d2P;
    float *dT32, *epT, *e0, *e1;
    int* pre;
    cudaGetSymbolAddress((void**)&WpI,  g_WpI);
    cudaGetSymbolAddress((void**)&Wp1,  g_Wp1);
    cudaGetSymbolAddress((void**)&Wp2,  g_Wp2);
    cudaGetSymbolAddress((void**)&WpO,  g_WpO);
    cudaGetSymbolAddress((void**)&fP,   g_fP);
    cudaGetSymbolAddress((void**)&dP,   g_dP);
    cudaGetSymbolAddress((void**)&f1P,  g_f1P);
    cudaGetSymbolAddress((void**)&d2P,  g_d2P);
    cudaGetSymbolAddress((void**)&dT32, g_dT32);
    cudaGetSymbolAddress((void**)&epT,  g_epT);
    cudaGetSymbolAddress((void**)&e0,   g_e0);
    cudaGetSymbolAddress((void**)&e1,   g_e1);
    cudaGetSymbolAddress((void**)&pre,  g_pre);

    cudaFuncSetAttribute(gf_gemm, cudaFuncAttributeMaxDynamicSharedMemorySize, SMEM_DYN);

    cudaMemcpyAsync(out + OFF_F0, feats0, (size_t)491520 * 4, cudaMemcpyDeviceToDevice, 0);
    cudaMemcpyAsync(out + OFF_F1, feats1, (size_t)491520 * 4, cudaMemcpyDeviceToDevice, 0);

    prep_w<<<(256 * 13 * 64) / 256, 256>>>(WpI, W_in, 256, 32, 13);
    prep_w<<<(512 * 52 * 64) / 256, 256>>>(Wp1, W1, 512, 256, 52);
    prep_w<<<(256 * 104 * 64) / 256, 256>>>(Wp2, W2, 256, 512, 104);
    prep_w<<<(128 * 52 * 64) / 256, 256>>>(WpO, Wo, 32, 256, 52);

    prep_feats<<<(NTOT * 64) / 256, 256>>>(fP, feats0);
    prep_feats<<<(NTOT * 64) / 256, 256>>>(fP + (size_t)NTOT * 64, feats1);

    // conv_in: nch=1, O=256 -> mode 0 (dT32 + dP)
    gf_gemm<<<dim3(120, 2), 256, SMEM_DYN>>>(WpI, fP, 1, 13, nei, 0,
        b_in, b_in, b_in, dT32, feats0, feats1, dT32, dP, 4);
    // layer1: nch=4, O=512 -> mode 1 (f1P)
    gf_gemm<<<dim3(120, 4), 256, SMEM_DYN>>>(Wp1, dP, 4, 52, nei, 1,
        b1, g1, be1, dT32, feats0, feats1, dT32, f1P, 8);
    // layer2: nch=8, O=256 -> mode 2 (residual dT32 -> d2P)
    gf_gemm<<<dim3(120, 2), 256, SMEM_DYN>>>(Wp2, f1P, 8, 104, nei, 2,
        b2, g2, be2, dT32, feats0, feats1, dT32, d2P, 4);
    // conv_out: nch=4, O=32(pad128) -> mode 3 (+feats -> epT)
    gf_gemm<<<dim3(120, 1), 256, SMEM_DYN>>>(WpO, d2P, 4, 52, nei, 3,
        bo, go, beo, dT32, feats0, feats1, epT, dP, 4);

    finalize_t<<<BATCH, 64>>>(epT, e0, out + OFF_E0, out + OFF_I0);
    finalize_t<<<BATCH, 64>>>(epT + (size_t)NTOT * 32, e1, out + OFF_E1, out + OFF_I1);

    des2dr_kernel<<<BATCH, 64>>>(e0, e1, permu, pre);
    final_kernel<<<1, 256>>>(pre, truei, out);
}

// round 17
// speedup vs baseline: 4.5596x; 1.1092x over previous
#include <cuda_runtime.h>
#include <cuda_fp16.h>
#include <math.h>
#include <stdint.h>

#define BATCH 256
#define GSZ   60
#define KSZ   13
#define NTOT  (BATCH * GSZ)    // 15360 per net
#define NTOT2 (2 * NTOT)       // 30720 both nets

#define OFF_F0 0
#define OFF_F1 491520
#define OFF_E0 983040
#define OFF_E1 1474560
#define OFF_I0 1966080
#define OFF_I1 1974272
#define OFF_AB 1982464
#define OFF_TI 1982465
#define OFF_PI 1982721

// Row layout: 64 fp16 channels = 128B data padded to 144B (9 x 16B chunks).
// Padded stride makes column accesses conflict-free without swizzle:
// chunk index (9r + c) mod 8 == (r + c) mod 8.
#define RBH 72   // halves per row (144 B)

// ---------------------------------------------------------------------------
// Device scratch.
// Weights: Wp[s][m][72] fp16 (stage-major so a CTA A-tile is contiguous).
// Acts:    actP[n][j][72] fp16, n = net*15360 + b*60 + g.
// ---------------------------------------------------------------------------
__device__ __half g_WpI[13 * 256 * RBH];
__device__ __half g_Wp1[52 * 512 * RBH];
__device__ __half g_Wp2[104 * 256 * RBH];
__device__ __half g_WpO[52 * 128 * RBH];
__device__ __half g_fP [NTOT2 * 1 * RBH];
__device__ __half g_dP [(size_t)NTOT2 * 4 * RBH];
__device__ __half g_f1P[(size_t)NTOT2 * 8 * RBH];
__device__ __half g_d2P[(size_t)NTOT2 * 4 * RBH];
__device__ float g_dT32[(size_t)NTOT2 * 256];
__device__ float g_epT [NTOT2 * 32];
__device__ float g_e0  [BATCH * 32 * GSZ];
__device__ float g_e1  [BATCH * 32 * GSZ];
__device__ int   g_pre [BATCH];

// ---- helpers ----
__device__ __forceinline__ uint32_t smem_u32(const void* p) {
    uint32_t a;
    asm("{ .reg .u64 t; cvta.to.shared.u64 t, %1; cvt.u32.u64 %0, t; }" : "=r"(a) : "l"(p));
    return a;
}
__device__ __forceinline__ void mbar_init(uint32_t m, uint32_t c) {
    asm volatile("mbarrier.init.shared.b64 [%0], %1;" :: "r"(m), "r"(c) : "memory");
}
__device__ __forceinline__ void mbar_expect_tx(uint32_t m, uint32_t tx) {
    asm volatile("mbarrier.arrive.expect_tx.shared.b64 _, [%0], %1;"
                 :: "r"(m), "r"(tx) : "memory");
}
__device__ __forceinline__ void mbar_wait(uint32_t m, uint32_t par) {
    asm volatile(
        "{\n\t.reg .pred P;\n\t"
        "WL%=:\n\t"
        "mbarrier.try_wait.parity.acquire.cta.shared::cta.b64 P, [%0], %1, 0x989680;\n\t"
        "@P bra.uni WD%=;\n\t"
        "bra.uni WL%=;\n\t"
        "WD%=:\n\t}" :: "r"(m), "r"(par) : "memory");
}
__device__ __forceinline__ void bulk_g2s(uint32_t dst, const void* src, uint32_t sz, uint32_t mbar) {
    asm volatile(
        "cp.async.bulk.shared::cluster.global.mbarrier::complete_tx::bytes [%0], [%1], %2, [%3];"
        :: "r"(dst), "l"(src), "r"(sz), "r"(mbar) : "memory");
}
__device__ __forceinline__ void ldsm4(uint32_t* r, uint32_t a) {
    asm volatile("ldmatrix.sync.aligned.m8n8.x4.shared.b16 {%0,%1,%2,%3}, [%4];"
                 : "=r"(r[0]), "=r"(r[1]), "=r"(r[2]), "=r"(r[3]) : "r"(a));
}
__device__ __forceinline__ void ldsm2(uint32_t* r, uint32_t a) {
    asm volatile("ldmatrix.sync.aligned.m8n8.x2.shared.b16 {%0,%1}, [%2];"
                 : "=r"(r[0]), "=r"(r[1]) : "r"(a));
}
__device__ __forceinline__ void mma_fp16(float* d, const uint32_t* a, const uint32_t* b) {
    asm volatile(
        "mma.sync.aligned.m16n8k16.row.col.f32.f16.f16.f32 "
        "{%0,%1,%2,%3},{%4,%5,%6,%7},{%8,%9},{%0,%1,%2,%3};"
        : "+f"(d[0]), "+f"(d[1]), "+f"(d[2]), "+f"(d[3])
        : "r"(a[0]), "r"(a[1]), "r"(a[2]), "r"(a[3]), "r"(b[0]), "r"(b[1]));
}

// ---- prep: W[o][cr][k] -> Wp[s][o][72] fp16, s=j*13+k ----
__global__ __launch_bounds__(256) void prep_w(
    __half* __restrict__ dst, const float* __restrict__ W,
    int Oreal, int Creal, int nstages, int Opad)
{
    int idx = blockIdx.x * 256 + threadIdx.x;
    int c = idx & 63;
    int s = (idx >> 6) % nstages;
    int o = idx / (64 * nstages);
    int k = s % 13, j = s / 13;
    int cr = j * 64 + c;
    float v = 0.f;
    if (o < Oreal && cr < Creal) v = W[((size_t)o * Creal + cr) * 13 + k];
    dst[((size_t)s * Opad + o) * RBH + c] = __float2half(v);
}

// ---- prep: feats[b][c][g] -> dst[n][72] ----
__global__ __launch_bounds__(256) void prep_feats(
    __half* __restrict__ dst, const float* __restrict__ f)
{
    int idx = blockIdx.x * 256 + threadIdx.x;   // < 15360*64
    int c = idx & 63;
    int n = idx >> 6;
    int b = n / 60, g = n - b * 60;
    float v = (c < 32) ? f[(size_t)b * 1920 + c * 60 + g] : 0.f;
    dst[(size_t)n * RBH + c] = __float2half(v);
}

// ---------------------------------------------------------------------------
// Gather-fused GEMM, single-pass fp16, cp.async.bulk staging.
// CTA tile M=128 x N=256; 8 warps (2M x 4N), warp tile 64x64.
// Stage = one (chunk j, k): A = one 18432B bulk (contiguous, stage-major Wp),
// B = 256 gathered rows x one 144B bulk each. 3-deep mbarrier ring.
// Padded 144B row stride -> conflict-free ldmatrix, no swizzle.
// ---------------------------------------------------------------------------
#define A_BYTES  18432              // 128 * 144
#define B_BYTES  36864              // 256 * 144
#define STG_SZ   (A_BYTES + B_BYTES)  // 55296
#define NSTAGE   3
#define OFF_MBAR 13312
#define OFF_STG  16384
#define SMEM_DYN (OFF_STG + NSTAGE * STG_SZ)   // 182272

__global__ __launch_bounds__(256, 1) void gf_gemm(
    const __half* __restrict__ Wp, const __half* __restrict__ actP,
    int nch, int nstages, int Mtot, const int* __restrict__ nei, int mode,
    const float* __restrict__ bias, const float* __restrict__ gamma,
    const float* __restrict__ beta, const float* __restrict__ dres,
    const float* __restrict__ feats0, const float* __restrict__ feats1,
    float* __restrict__ out32, __half* __restrict__ actOut, int nchO)
{
    extern __shared__ __align__(1024) char smem[];
    int* lut = (int*)smem;                    // [13][256] absolute act row index
    const uint32_t su = smem_u32(smem);
    const int tid = threadIdx.x;
    const int warp = tid >> 5, lane = tid & 31;
    const int n0 = blockIdx.x * 256;          // global position (both nets)
    const int m0 = blockIdx.y * 128;

    {
        const int n = n0 + tid;
        const int net = n / NTOT;
        const int nw = n - net * NTOT;
        const int b = nw / 60, g = nw - b * 60;
        #pragma unroll
        for (int k = 0; k < KSZ; ++k)
            lut[k * 256 + tid] = net * NTOT + b * 60 + nei[g * KSZ + k];
    }
    if (tid == 0) {
        #pragma unroll
        for (int i = 0; i < NSTAGE; ++i)
            mbar_init(su + OFF_MBAR + i * 8, 1);
    }
    __syncthreads();

    auto load_stage = [&](int s) {
        const int slot = s % NSTAGE;
        const uint32_t bufs = su + OFF_STG + (uint32_t)slot * STG_SZ;
        const uint32_t mbar = su + OFF_MBAR + (uint32_t)slot * 8;
        if (tid == 0) {
            mbar_expect_tx(mbar, STG_SZ);
            // A: one contiguous bulk (stage-major weight layout)
            bulk_g2s(bufs, (const char*)(Wp + ((size_t)s * Mtot + m0) * RBH),
                     A_BYTES, mbar);
        }
        // B: one gathered 144B row per thread
        const int k = s % 13, j = s / 13;
        const int sr = lut[k * 256 + tid];
        bulk_g2s(bufs + A_BYTES + (uint32_t)tid * 144,
                 (const char*)(actP + ((size_t)sr * nch + j) * RBH), 144, mbar);
    };

    // prologue: fill the ring (all layers have nstages >= NSTAGE)
    load_stage(0);
    load_stage(1);
    load_stage(2);

    const int wm = warp >> 2, wn = warp & 3;
    float acc[4][8][4] = {};

    const uint32_t arow = (uint32_t)(wm * 64 + (lane & 15));
    const uint32_t acolx = (uint32_t)((lane >> 4) * 16);
    const uint32_t brow = (uint32_t)(wn * 64 + (lane & 7));
    const uint32_t bcolx = (uint32_t)(((lane >> 3) & 1) * 16);

    for (int s = 0; s < nstages; ++s) {
        const int slot = s % NSTAGE;
        mbar_wait(su + OFF_MBAR + (uint32_t)slot * 8, (s / NSTAGE) & 1);
        const uint32_t bufs = su + OFF_STG + (uint32_t)slot * STG_SZ;
        const uint32_t Ap = bufs, Bp = bufs + A_BYTES;

        #pragma unroll
        for (int ks = 0; ks < 4; ++ks) {
            const uint32_t kb = ks * 32;
            uint32_t ap[4][4], bp[8][2];
            #pragma unroll
            for (int mt = 0; mt < 4; ++mt)
                ldsm4(ap[mt], Ap + (arow + mt * 16) * 144 + kb + acolx);
            #pragma unroll
            for (int nt = 0; nt < 8; ++nt)
                ldsm2(bp[nt], Bp + (brow + nt * 8) * 144 + kb + bcolx);
            #pragma unroll
            for (int mt = 0; mt < 4; ++mt)
                #pragma unroll
                for (int nt = 0; nt < 8; ++nt)
                    mma_fp16(acc[mt][nt], ap[mt], bp[nt]);
        }
        __syncthreads();          // all readers done with this slot
        if (s + NSTAGE < nstages) load_stage(s + NSTAGE);
    }

    // ---- epilogue ----
    const int g4 = lane >> 2, t4 = lane & 3;
    #pragma unroll
    for (int mt = 0; mt < 4; ++mt) {
        #pragma unroll
        for (int dr = 0; dr < 2; ++dr) {
            const int o = m0 + wm * 64 + mt * 16 + g4 + dr * 8;
            if (mode == 3 && o >= 32) continue;
            const float bv = bias[o];
            float gv = 0.f, bev = 0.f;
            if (mode != 0) { gv = gamma[o]; bev = beta[o]; }
            const int jo = o >> 6, co = o & 63;
            #pragma unroll
            for (int nt = 0; nt < 8; ++nt) {
                #pragma unroll
                for (int dn = 0; dn < 2; ++dn) {
                    const float sv = acc[mt][nt][dr * 2 + dn] + bv;
                    const int n = n0 + wn * 64 + nt * 8 + t4 * 2 + dn;
                    if (mode == 0) {
                        out32[(size_t)n * 256 + o] = sv;
                        actOut[((size_t)n * nchO + jo) * RBH + co] = __float2half(sv);
                    } else if (mode == 1) {
                        const float v = fmaxf(sv * gv + bev, 0.f);
                        actOut[((size_t)n * nchO + jo) * RBH + co] = __float2half(v);
                    } else if (mode == 2) {
                        const float v = fmaxf(sv * gv + bev, 0.f) + dres[(size_t)n * 256 + o];
                        actOut[((size_t)n * nchO + jo) * RBH + co] = __float2half(v);
                    } else {
                        const int netl = n / NTOT;
                        const int nw = n - netl * NTOT;
                        const int b = nw / 60, gg = nw - b * 60;
                        const float* fsrc = netl ? feats1 : feats0;
                        out32[(size_t)n * 32 + o] =
                            fmaxf(sv * gv + bev, 0.f) + fsrc[(size_t)b * 1920 + o * 60 + gg];
                    }
                }
            }
        }
    }
}

// ---- finalize: epT[(b,g)][32] -> inv + normalized eqv [b][c][g] ----
__global__ __launch_bounds__(64) void finalize_t(
    const float* __restrict__ epT, float* __restrict__ e_store,
    float* __restrict__ out_eqv, float* __restrict__ out_inv)
{
    __shared__ float s[1920];
    __shared__ float norms[60];
    __shared__ float invv[32];
    __shared__ float ninv;
    const int b = blockIdx.x, t = threadIdx.x;

    for (int i = t; i < 1920; i += 64) s[i] = epT[(size_t)b * 1920 + i];
    __syncthreads();
    if (t < 60) {
        float a = 0.f;
        #pragma unroll
        for (int c = 0; c < 32; ++c) { float v = s[t * 32 + c]; a += v * v; }
        norms[t] = fmaxf(sqrtf(a), 1e-4f);
    }
    if (t < 32) {
        float a = 0.f;
        for (int g = 0; g < 60; ++g) a += s[g * 32 + t];
        invv[t] = a * (1.f / 60.f);
    }
    __syncthreads();
    if (t == 0) {
        float a = 0.f;
        #pragma unroll
        for (int c = 0; c < 32; ++c) a += invv[c] * invv[c];
        ninv = fmaxf(sqrtf(a), 1e-4f);
    }
    __syncthreads();
    if (t < 32) out_inv[b * 32 + t] = invv[t] / ninv;
    for (int i = t; i < 1920; i += 64) {
        const int g = i >> 5, c = i & 31;
        const float v = s[i] / norms[g];
        const size_t oi = (size_t)b * 1920 + c * 60 + g;
        out_eqv[oi] = v;
        e_store[oi] = v;
    }
}

// ---- des2dr ----
__global__ __launch_bounds__(64) void des2dr_kernel(
    const float* __restrict__ e0, const float* __restrict__ e1,
    const int* __restrict__ permu, int* __restrict__ pre)
{
    __shared__ float s0[1920], s1[1920];
    __shared__ float cor[60];
    __shared__ int sp[3600];
    const int b = blockIdx.x, t = threadIdx.x;

    for (int i = t; i < 1920; i += 64) {
        s0[i] = e0[(size_t)b * 1920 + i];
        s1[i] = e1[(size_t)b * 1920 + i];
    }
    for (int i = t; i < 3600; i += 64) sp[i] = permu[i];
    __syncthreads();

    if (t < 60) {
        float a = 0.f;
        for (int g = 0; g < 60; ++g) {
            const int p = sp[t * 60 + g];
            #pragma unroll 8
            for (int f = 0; f < 32; ++f) a += s0[f * 60 + p] * s1[f * 60 + g];
        }
        cor[t] = a;
    }
    __syncthreads();
    if (t == 0) {
        float best = cor[0]; int bi = 0;
        for (int a = 1; a < 60; ++a) if (cor[a] > best) { best = cor[a]; bi = a; }
        pre[b] = bi;
    }
}

// ---- ability + integer outputs ----
__global__ __launch_bounds__(256) void final_kernel(
    const int* __restrict__ pre, const int* __restrict__ truei,
    float* __restrict__ out)
{
    __shared__ int cnt[256];
    const int t = threadIdx.x;
    cnt[t] = (pre[t] == truei[t]) ? 1 : 0;
    __syncthreads();
    for (int s = 128; s > 0; s >>= 1) {
        if (t < s) cnt[t] += cnt[t + s];
        __syncthreads();
    }
    if (t == 0) out[OFF_AB] = (float)cnt[0] / 256.f;
    out[OFF_TI + t] = (float)truei[t];
    out[OFF_PI + t] = (float)pre[t];
}

// ---------------------------------------------------------------------------
extern "C" void kernel_launch(void* const* d_in, const int* in_sizes, int n_in,
                              void* d_out, int out_size)
{
    const float* feats0 = (const float*)d_in[0];
    const float* feats1 = (const float*)d_in[1];
    const int*   truei  = (const int*)  d_in[2];
    const int*   nei    = (const int*)  d_in[3];
    const int*   permu  = (const int*)  d_in[4];
    const float* W_in = (const float*)d_in[5];  const float* b_in = (const float*)d_in[6];
    const float* W1   = (const float*)d_in[7];  const float* b1   = (const float*)d_in[8];
    const float* g1   = (const float*)d_in[9];  const float* be1  = (const float*)d_in[10];
    const float* W2   = (const float*)d_in[11]; const float* b2   = (const float*)d_in[12];
    const float* g2   = (const float*)d_in[13]; const float* be2  = (const float*)d_in[14];
    const float* Wo   = (const float*)d_in[15]; const float* bo   = (const float*)d_in[16];
    const float* go   = (const float*)d_in[17]; const float* beo  = (const float*)d_in[18];
    float* out = (float*)d_out;

    __half *WpI, *Wp1, *Wp2, *WpO, *fP, *dP, *f1P, *d2P;
    float *dT32, *epT, *e0, *e1;
    int* pre;
    cudaGetSymbolAddress((void**)&WpI,  g_WpI);
    cudaGetSymbolAddress((void**)&Wp1,  g_Wp1);
    cudaGetSymbolAddress((void**)&Wp2,  g_Wp2);
    cudaGetSymbolAddress((void**)&WpO,  g_WpO);
    cudaGetSymbolAddress((void**)&fP,   g_fP);
    cudaGetSymbolAddress((void**)&dP,   g_dP);
    cudaGetSymbolAddress((void**)&f1P,  g_f1P);
    cudaGetSymbolAddress((void**)&d2P,  g_d2P);
    cudaGetSymbolAddress((void**)&dT32, g_dT32);
    cudaGetSymbolAddress((void**)&epT,  g_epT);
    cudaGetSymbolAddress((void**)&e0,   g_e0);
    cudaGetSymbolAddress((void**)&e1,   g_e1);
    cudaGetSymbolAddress((void**)&pre,  g_pre);

    cudaFuncSetAttribute(gf_gemm, cudaFuncAttributeMaxDynamicSharedMemorySize, SMEM_DYN);

    cudaMemcpyAsync(out + OFF_F0, feats0, (size_t)491520 * 4, cudaMemcpyDeviceToDevice, 0);
    cudaMemcpyAsync(out + OFF_F1, feats1, (size_t)491520 * 4, cudaMemcpyDeviceToDevice, 0);

    prep_w<<<(256 * 13 * 64) / 256, 256>>>(WpI, W_in, 256, 32, 13, 256);
    prep_w<<<(512 * 52 * 64) / 256, 256>>>(Wp1, W1, 512, 256, 52, 512);
    prep_w<<<(256 * 104 * 64) / 256, 256>>>(Wp2, W2, 256, 512, 104, 256);
    prep_w<<<(128 * 52 * 64) / 256, 256>>>(WpO, Wo, 32, 256, 52, 128);

    prep_feats<<<(NTOT * 64) / 256, 256>>>(fP, feats0);
    prep_feats<<<(NTOT * 64) / 256, 256>>>(fP + (size_t)NTOT * RBH, feats1);

    // conv_in: nch=1, O=256 -> mode 0 (dT32 + dP)
    gf_gemm<<<dim3(120, 2), 256, SMEM_DYN>>>(WpI, fP, 1, 13, 256, nei, 0,
        b_in, b_in, b_in, dT32, feats0, feats1, dT32, dP, 4);
    // layer1: nch=4, O=512 -> mode 1 (f1P)
    gf_gemm<<<dim3(120, 4), 256, SMEM_DYN>>>(Wp1, dP, 4, 52, 512, nei, 1,
        b1, g1, be1, dT32, feats0, feats1, dT32, f1P, 8);
    // layer2: nch=8, O=256 -> mode 2 (residual dT32 -> d2P)
    gf_gemm<<<dim3(120, 2), 256, SMEM_DYN>>>(Wp2, f1P, 8, 104, 256, nei, 2,
        b2, g2, be2, dT32, feats0, feats1, dT32, d2P, 4);
    // conv_out: nch=4, O=32(pad128) -> mode 3 (+feats -> epT)
    gf_gemm<<<dim3(120, 1), 256, SMEM_DYN>>>(WpO, d2P, 4, 52, 128, nei, 3,
        bo, go, beo, dT32, feats0, feats1, epT, dP, 4);

    finalize_t<<<BATCH, 64>>>(epT, e0, out + OFF_E0, out + OFF_I0);
    finalize_t<<<BATCH, 64>>>(epT + (size_t)NTOT * 32, e1, out + OFF_E1, out + OFF_I1);

    des2dr_kernel<<<BATCH, 64>>>(e0, e1, permu, pre);
    final_kernel<<<1, 256>>>(pre, truei, out);
}